// round 13
// baseline (speedup 1.0000x reference)
#include <cuda_runtime.h>
#include <cuda_bf16.h>
#include <math.h>
#include <stdint.h>

#define BB      32
#define TT      64
#define NEV     2048      // B*T events
#define NOCC    4096      // 2*B*T occurrences
#define DIMD    128
#define DIMC    64
#define DIML    256
#define FEAT    320
#define INDIM   449
#define ES      464       // padded e row stride (div by 16)
#define NH      4
#define DH      80
#define NWAVES  16
#define OUT_FULL 25802049  // 1 + 2048 + 200000*128 + 200000

// ------------------------ device scratch ------------------------------------
__device__ int   g_prevRead[NOCC];
__device__ int   g_isLast[NOCC];
__device__ int   g_depth[NEV];
__device__ int   g_order[NEV];
__device__ int   g_waveStart[NWAVES + 1];
__device__ int   g_bar[NWAVES];
__device__ float g_dts[NEV];
__device__ float g_dto[NEV];
__device__ float g_inp[NEV * FEAT];
__device__ float g_h[NEV * DIML];
__device__ float g_newS[NEV * DIMD];
__device__ float g_newO[NEV * DIMD];
__device__ float g_x[NEV * FEAT];
__device__ float g_e[NEV * ES + 64];
__device__ float g_q[NEV * FEAT];
__device__ float g_k[NEV * FEAT];
__device__ float g_v[NEV * FEAT];
__device__ float g_ao[NEV * FEAT];
__device__ float g_s1[NEV * DIMD];
__device__ float g_loss[NEV];

__device__ __forceinline__ float sigm(float x) { return 1.f / (1.f + expf(-x)); }

__device__ __forceinline__ uint32_t f2tf32(float f) {
    uint32_t u; asm("cvt.rna.tf32.f32 %0, %1;" : "=r"(u) : "f"(f)); return u;
}
__device__ __forceinline__ void mma_tf32(float* c, uint32_t a0, uint32_t a1,
                                         uint32_t a2, uint32_t a3,
                                         uint32_t b0, uint32_t b1) {
    asm volatile(
        "mma.sync.aligned.m16n8k8.row.col.f32.tf32.tf32.f32 "
        "{%0,%1,%2,%3}, {%4,%5,%6,%7}, {%8,%9}, {%0,%1,%2,%3};"
        : "+f"(c[0]), "+f"(c[1]), "+f"(c[2]), "+f"(c[3])
        : "r"(a0), "r"(a1), "r"(a2), "r"(a3), "r"(b0), "r"(b1));
}

// ------------------------ kernel A1: occurrence links -----------------------
__global__ void links_kernel(const int* __restrict__ subj, const int* __restrict__ obj,
                             const float* __restrict__ tim, const float* __restrict__ lt)
{
    __shared__ int s_ent[NOCC];
    int tid = threadIdx.x;
    for (int p = tid; p < NOCC; p += 256) {
        int t = p >> 6, r = p & 63, ph = r >> 5, b = r & 31;
        s_ent[p] = ph ? obj[b * TT + t] : subj[b * TT + t];
    }
    __syncthreads();
    int pos = blockIdx.x * 256 + tid;
    int e = s_ent[pos];
    int t = pos >> 6, r = pos & 63, ph = r >> 5, b = r & 31;
    int stepStart = t * 64;
    int prevR = -1, later = 0;
    for (int p2 = 0; p2 < NOCC; p2++) {
        if (s_ent[p2] == e) {
            if (p2 < stepStart) prevR = p2;
            if (p2 > pos) later = 1;
        }
    }
    g_prevRead[pos] = prevR;
    g_isLast[pos] = !later;
    float ltv = (prevR < 0) ? lt[e] : tim[(prevR & 31) * TT + (prevR >> 6)];
    float dt = tim[b * TT + t] - ltv;
    int ev = t * 32 + b;
    if (ph == 0) g_dts[ev] = dt; else g_dto[ev] = dt;
}

// ------------------------ kernel A2: depths + compaction ---------------------
__global__ void depth_compact_kernel()
{
    __shared__ int s_d[NEV];
    __shared__ int s_ps[NEV];
    __shared__ int s_po[NEV];
    __shared__ int s_cnt[NWAVES];
    __shared__ int s_off[NWAVES + 1];
    __shared__ int s_n;
    int tid = threadIdx.x;
    for (int ev = tid; ev < NEV; ev += 256) {
        int t = ev >> 5, b = ev & 31;
        int ps = g_prevRead[t * 64 + b];
        int po = g_prevRead[t * 64 + 32 + b];
        s_ps[ev] = (ps < 0) ? -1 : ((ps >> 6) * 32 + (ps & 31));
        s_po[ev] = (po < 0) ? -1 : ((po >> 6) * 32 + (po & 31));
        s_d[ev] = -1;
    }
    if (tid < NWAVES) { s_cnt[tid] = 0; g_bar[tid] = 0; }
    if (tid == 0) s_n = 0;
    __syncthreads();
    for (int pass = 0; pass < 32; pass++) {
        for (int ev = tid; ev < NEV; ev += 256) {
            if (s_d[ev] < 0) {
                int a = s_ps[ev], b2 = s_po[ev];
                int da = (a < 0) ? -1 : s_d[a];
                int db = (b2 < 0) ? -1 : s_d[b2];
                bool ra = (a < 0) || (da >= 0);
                bool rb = (b2 < 0) || (db >= 0);
                if (ra && rb) { s_d[ev] = max(da, db) + 1; atomicAdd(&s_n, 1); }
            }
        }
        __syncthreads();
        if (s_n >= NEV) break;
    }
    for (int ev = tid; ev < NEV; ev += 256) {
        int d = s_d[ev];
        d = (d < 0) ? 0 : ((d > NWAVES - 1) ? NWAVES - 1 : d);
        s_d[ev] = d;
        g_depth[ev] = d;
        atomicAdd(&s_cnt[d], 1);
    }
    __syncthreads();
    if (tid == 0) {
        int acc = 0;
        for (int w = 0; w < NWAVES; w++) { s_off[w] = acc; acc += s_cnt[w]; }
        s_off[NWAVES] = acc;
        for (int w = 0; w <= NWAVES; w++) g_waveStart[w] = s_off[w];
        for (int w = 0; w < NWAVES; w++) s_cnt[w] = s_off[w];
    }
    __syncthreads();
    for (int ev = tid; ev < NEV; ev += 256) {
        int pos = atomicAdd(&s_cnt[s_d[ev]], 1);
        g_order[pos] = ev;
    }
}

// ------------------------ gather wave-0 inputs -------------------------------
__global__ void gather0_kernel(const int* __restrict__ subj, const int* __restrict__ obj,
                               const int* __restrict__ rel,
                               const float* __restrict__ mem, const float* __restrict__ remb)
{
    int idx = blockIdx.x * 256 + threadIdx.x;
    if (idx >= NEV * FEAT) return;
    int row = idx / FEAT, f = idx - row * FEAT;
    if (row >= g_waveStart[1]) return;
    int ev = g_order[row];
    int t = ev >> 5, b = ev & 31;
    float val;
    if (f < 256) {
        int which = f >> 7, ff = f & 127;
        int ent = which ? obj[b * TT + t] : subj[b * TT + t];
        val = mem[(size_t)ent * DIMD + ff];
    } else {
        val = remb[rel[b * TT + t] * DIMC + (f - 256)];
    }
    g_inp[row * FEAT + f] = val;
}

// ------------------------ tf32 tensor-core GEMM (128x64 tile) ----------------
// epi: 0 store; 2 relu(acc+bias); 3 sigm store; 4 dual-sigmoid wave scatter;
//      5 C += tanh(acc) AND mirror into g_e
__device__ __forceinline__ void mma128_body(
    const float* __restrict__ A, int lda,
    const float* __restrict__ Bm, int ldb, int Kb,
    float* __restrict__ C, int ldc, int K, int epi,
    const float* __restrict__ bias, const float* __restrict__ bias2, int limit)
{
    __shared__ uint32_t As[16][136];   // [k][m], stride 136 -> conflict-free frags
    __shared__ uint32_t Bs2[16][68];   // [k][(n%8)*8 + n/8]
    int tid = threadIdx.x;
    int lane = tid & 31, warp = tid >> 5;
    int tg = lane & 3, gid = lane >> 2;
    int row0 = blockIdx.y * 128;
    int col0 = blockIdx.x * 64;
    if (row0 >= limit) return;
    int mw = warp * 16;
    int gid8 = gid * 8;

    float acc[8][4];
    #pragma unroll
    for (int j = 0; j < 8; j++)
        #pragma unroll
        for (int c = 0; c < 4; c++) acc[j][c] = 0.f;

    int arow = tid >> 1;            // 0..127
    int akoff = (tid & 1) * 8;      // 0 or 8
    int bk = tid >> 4;              // 0..15
    int bn = (tid & 15) * 4;        // 0..60

    for (int kt = 0; kt < K; kt += 16) {
        const float* ap = A + (size_t)(row0 + arow) * lda + kt + akoff;
        float4 av0 = *(const float4*)(ap);
        float4 av1 = *(const float4*)(ap + 4);
        As[akoff + 0][arow] = f2tf32(av0.x);
        As[akoff + 1][arow] = f2tf32(av0.y);
        As[akoff + 2][arow] = f2tf32(av0.z);
        As[akoff + 3][arow] = f2tf32(av0.w);
        As[akoff + 4][arow] = f2tf32(av1.x);
        As[akoff + 5][arow] = f2tf32(av1.y);
        As[akoff + 6][arow] = f2tf32(av1.z);
        As[akoff + 7][arow] = f2tf32(av1.w);
        int gk = kt + bk;
        float4 bv = make_float4(0.f, 0.f, 0.f, 0.f);
        if (gk < Kb) bv = *(const float4*)(Bm + (size_t)gk * ldb + col0 + bn);
        Bs2[bk][((bn + 0) & 7) * 8 + ((bn + 0) >> 3)] = f2tf32(bv.x);
        Bs2[bk][((bn + 1) & 7) * 8 + ((bn + 1) >> 3)] = f2tf32(bv.y);
        Bs2[bk][((bn + 2) & 7) * 8 + ((bn + 2) >> 3)] = f2tf32(bv.z);
        Bs2[bk][((bn + 3) & 7) * 8 + ((bn + 3) >> 3)] = f2tf32(bv.w);
        __syncthreads();
        #pragma unroll
        for (int ks = 0; ks < 16; ks += 8) {
            uint32_t a0 = As[ks + tg][mw + gid];
            uint32_t a1 = As[ks + tg][mw + gid + 8];
            uint32_t a2 = As[ks + tg + 4][mw + gid];
            uint32_t a3 = As[ks + tg + 4][mw + gid + 8];
            uint4 B0a = *(const uint4*)&Bs2[ks + tg][gid8];
            uint4 B0b = *(const uint4*)&Bs2[ks + tg][gid8 + 4];
            uint4 B1a = *(const uint4*)&Bs2[ks + tg + 4][gid8];
            uint4 B1b = *(const uint4*)&Bs2[ks + tg + 4][gid8 + 4];
            mma_tf32(acc[0], a0, a1, a2, a3, B0a.x, B1a.x);
            mma_tf32(acc[1], a0, a1, a2, a3, B0a.y, B1a.y);
            mma_tf32(acc[2], a0, a1, a2, a3, B0a.z, B1a.z);
            mma_tf32(acc[3], a0, a1, a2, a3, B0a.w, B1a.w);
            mma_tf32(acc[4], a0, a1, a2, a3, B0b.x, B1b.x);
            mma_tf32(acc[5], a0, a1, a2, a3, B0b.y, B1b.y);
            mma_tf32(acc[6], a0, a1, a2, a3, B0b.z, B1b.z);
            mma_tf32(acc[7], a0, a1, a2, a3, B0b.w, B1b.w);
        }
        __syncthreads();
    }

    #pragma unroll
    for (int j = 0; j < 8; j++) {
        int cc = col0 + j * 8 + tg * 2;
        int r0 = row0 + mw + gid;
        int r1 = r0 + 8;
        if (epi == 0) {
            *(float2*)&C[(size_t)r0 * ldc + cc] = make_float2(acc[j][0], acc[j][1]);
            *(float2*)&C[(size_t)r1 * ldc + cc] = make_float2(acc[j][2], acc[j][3]);
        } else if (epi == 5) {
            float n0 = C[(size_t)r0 * ldc + cc]     + tanhf(acc[j][0]);
            float n1 = C[(size_t)r0 * ldc + cc + 1] + tanhf(acc[j][1]);
            float n2 = C[(size_t)r1 * ldc + cc]     + tanhf(acc[j][2]);
            float n3 = C[(size_t)r1 * ldc + cc + 1] + tanhf(acc[j][3]);
            C[(size_t)r0 * ldc + cc]     = n0;  g_e[(size_t)r0 * ES + cc]     = n0;
            C[(size_t)r0 * ldc + cc + 1] = n1;  g_e[(size_t)r0 * ES + cc + 1] = n1;
            C[(size_t)r1 * ldc + cc]     = n2;  g_e[(size_t)r1 * ES + cc]     = n2;
            C[(size_t)r1 * ldc + cc + 1] = n3;  g_e[(size_t)r1 * ES + cc + 1] = n3;
        } else {
            #pragma unroll
            for (int half = 0; half < 2; half++) {
                int rr = half ? r1 : r0;
                if (rr >= limit) continue;
                #pragma unroll
                for (int q = 0; q < 2; q++) {
                    float v = acc[j][half * 2 + q];
                    int ccq = cc + q;
                    if (epi == 2)      C[(size_t)rr * ldc + ccq] = fmaxf(v + bias[ccq], 0.f);
                    else if (epi == 3) C[(size_t)rr * ldc + ccq] = sigm(v);
                    else {             // epi 4
                        int ev = g_order[rr];
                        g_newS[ev * DIMD + ccq] = sigm(g_dts[ev] * bias[ccq]  + v);
                        g_newO[ev * DIMD + ccq] = sigm(g_dto[ev] * bias2[ccq] + v);
                    }
                }
            }
        }
    }
}

__global__ void __launch_bounds__(256) qkv_mma_kernel(
    const float* __restrict__ A,
    const float* __restrict__ B0, const float* __restrict__ B1, const float* __restrict__ B2,
    float* __restrict__ C0, float* __restrict__ C1, float* __restrict__ C2)
{
    const float* Bm = (blockIdx.z == 0) ? B0 : (blockIdx.z == 1) ? B1 : B2;
    float* C = (blockIdx.z == 0) ? C0 : (blockIdx.z == 1) ? C1 : C2;
    mma128_body(A, ES, Bm, FEAT, INDIM, C, FEAT, ES, 0, nullptr, nullptr, NEV);
}

__global__ void __launch_bounds__(256) wo_mma_kernel(
    const float* __restrict__ A, const float* __restrict__ Bm, float* __restrict__ C)
{
    mma128_body(A, FEAT, Bm, FEAT, FEAT, C, FEAT, FEAT, 5, nullptr, nullptr, NEV);
}

// generic: Wh (epi 3), Whh (epi 4), score-W1 (epi 2)
__global__ void __launch_bounds__(256) mma_gen_kernel(
    const float* __restrict__ A, int lda,
    const float* __restrict__ Bm, int ldb, int Kb,
    float* __restrict__ C, int ldc, int K, int epi,
    const float* __restrict__ bias, const float* __restrict__ bias2, int useLimit)
{
    int limit = useLimit ? g_waveStart[1] : NEV;
    mma128_body(A, lda, Bm, ldb, Kb, C, ldc, K, epi, bias, bias2, limit);
}

// ------------------------ cleanup: waves >= 1 (persistent, 16 blocks) --------
__global__ void __launch_bounds__(256) cleanup_kernel(
    const int* __restrict__ subj, const int* __restrict__ obj,
    const int* __restrict__ rel,
    const float* __restrict__ mem, const float* __restrict__ remb,
    const float* __restrict__ Wh, const float* __restrict__ Whh,
    const float* __restrict__ Wst, const float* __restrict__ Wot)
{
    __shared__ float s_inp[FEAT];
    __shared__ float s_h[DIML];
    int tid = threadIdx.x;
    for (int w = 1; w < NWAVES; w++) {
        int ws = g_waveStart[w], we = g_waveStart[w + 1];
        if (ws >= NEV) break;
        for (int i = ws + blockIdx.x; i < we; i += 16) {
            int ev = g_order[i];
            int t = ev >> 5, b = ev & 31;
            for (int f = tid; f < FEAT; f += 256) {
                float val;
                if (f < 256) {
                    int which = f >> 7, ff = f & 127;
                    int pred = g_prevRead[t * 64 + which * 32 + b];
                    if (pred < 0) {
                        int ent = which ? obj[b * TT + t] : subj[b * TT + t];
                        val = mem[(size_t)ent * DIMD + ff];
                    } else {
                        int pph = (pred >> 5) & 1;
                        int pev = (pred >> 6) * 32 + (pred & 31);
                        val = pph ? g_newO[pev * DIMD + ff] : g_newS[pev * DIMD + ff];
                    }
                } else {
                    val = remb[rel[b * TT + t] * DIMC + (f - 256)];
                }
                s_inp[f] = val;
            }
            __syncthreads();
            {
                float acc = 0.f;
                #pragma unroll 4
                for (int k = 0; k < FEAT; k++)
                    acc += s_inp[k] * Wh[(size_t)k * DIML + tid];
                s_h[tid] = sigm(acc);
            }
            __syncthreads();
            if (tid < DIMD) {
                float acc = 0.f;
                #pragma unroll 4
                for (int k = 0; k < DIML; k++)
                    acc += s_h[k] * Whh[(size_t)k * DIMD + tid];
                g_newS[ev * DIMD + tid] = sigm(g_dts[ev] * Wst[tid] + acc);
                g_newO[ev * DIMD + tid] = sigm(g_dto[ev] * Wot[tid] + acc);
            }
            __syncthreads();
        }
        __threadfence();
        __syncthreads();
        if (tid == 0) {
            atomicAdd(&g_bar[w], 1);
            while (atomicAdd(&g_bar[w], 0) < 16) { }
        }
        __syncthreads();
        __threadfence();
    }
}

// ------------------------ assemble evt rows (writes g_x AND g_e) -------------
__global__ void assemble_x_kernel(const int* __restrict__ rel,
                                  const float* __restrict__ remb)
{
    int idx = blockIdx.x * 256 + threadIdx.x;
    if (idx >= NEV * FEAT) return;
    int row = idx / FEAT, f = idx - row * FEAT;
    int b = row >> 6, t = row & 63;
    int ev = t * 32 + b;
    float val;
    if (f < 128)      val = g_newS[ev * DIMD + f];
    else if (f < 256) val = g_newO[ev * DIMD + (f - 128)];
    else              val = remb[rel[row] * DIMC + (f - 256)];
    g_x[idx] = val;
    g_e[(size_t)row * ES + f] = val;
}

// e tail cols: [320..448)=sin(time*norm), 448=1, 449..463=0  (written once)
__global__ void e_tail_kernel(const float* __restrict__ tim)
{
    int idx = blockIdx.x * 256 + threadIdx.x;
    int row = idx / 144, f = idx - row * 144;
    if (row >= NEV) return;
    int col = FEAT + f;
    float val;
    if (f < DIMD) {
        float p = powf(10000.0f, (float)f);
        float nrm = isinf(p) ? 0.0f : (1.0f / p);
        val = sinf(tim[row] * nrm);
    } else if (col == INDIM - 1) val = 1.0f;
    else val = 0.0f;
    g_e[(size_t)row * ES + col] = val;
}

// ------------------------ attention (per b,h block) --------------------------
__global__ void __launch_bounds__(256) attn_kernel()
{
    extern __shared__ float sm[];
    float* sq = sm;
    float* sk = sq + 64 * 84;
    float* sv = sk + 64 * 84;
    float* ssc = sv + 64 * 84;
    int b = blockIdx.x, h = blockIdx.y;
    int tid = threadIdx.x;
    const float scale = 0.111803398875f;

    for (int idx = tid; idx < 64 * DH; idx += 256) {
        int i = idx / DH, d = idx - i * DH;
        int row = b * TT + i, col = h * DH + d;
        sq[i * 84 + d] = g_q[(size_t)row * FEAT + col];
        sk[i * 84 + d] = g_k[(size_t)row * FEAT + col];
        sv[i * 84 + d] = g_v[(size_t)row * FEAT + col];
    }
    __syncthreads();
    {
        int i = tid >> 2, jg = tid & 3;
        float acc[16];
        #pragma unroll
        for (int jj = 0; jj < 16; jj++) acc[jj] = 0.f;
        for (int kk = 0; kk < 20; kk++) {
            float4 qv = *(const float4*)&sq[i * 84 + kk * 4];
            #pragma unroll
            for (int jj = 0; jj < 16; jj++) {
                int j = jg * 16 + jj;
                float4 kv = *(const float4*)&sk[j * 84 + kk * 4];
                acc[jj] += qv.x * kv.x + qv.y * kv.y + qv.z * kv.z + qv.w * kv.w;
            }
        }
        #pragma unroll
        for (int jj = 0; jj < 16; jj++)
            ssc[i * 68 + jg * 16 + jj] = acc[jj] * scale;
    }
    __syncthreads();
    if (tid < 64) {
        int i = tid;
        if (i == 0) {
            for (int j = 0; j < 64; j++) ssc[j] = 0.f;
        } else {
            float mx = -1e30f;
            for (int j = 0; j < i; j++) mx = fmaxf(mx, ssc[i * 68 + j]);
            float sum = 0.f;
            for (int j = 0; j < i; j++) sum += expf(ssc[i * 68 + j] - mx);
            float inv = 1.f / sum;
            for (int j = 0; j < i; j++) ssc[i * 68 + j] = expf(ssc[i * 68 + j] - mx) * inv;
            for (int j = i; j < 64; j++) ssc[i * 68 + j] = 0.f;
        }
    }
    __syncthreads();
    {
        int i = tid >> 2, dg = tid & 3, d0 = dg * 20;
        float acc[20];
        #pragma unroll
        for (int dd = 0; dd < 20; dd++) acc[dd] = 0.f;
        for (int j = 0; j < 64; j++) {
            float a = ssc[i * 68 + j];
            #pragma unroll
            for (int dd = 0; dd < 20; dd++)
                acc[dd] += a * sv[j * 84 + d0 + dd];
        }
        int row = b * TT + i;
        #pragma unroll
        for (int dd = 0; dd < 20; dd++)
            g_ao[(size_t)row * FEAT + h * DH + d0 + dd] = acc[dd];
    }
}

// ------------------------ score head -----------------------------------------
__global__ void score2_kernel(const float* __restrict__ W2, const float* __restrict__ b2,
                              float* __restrict__ dout, int full)
{
    int gt = blockIdx.x * blockDim.x + threadIdx.x;
    int warp = gt >> 5, lane = gt & 31;
    if (warp >= NEV) return;
    float acc = 0.f;
    for (int f = lane; f < DIMD; f += 32)
        acc += g_s1[warp * DIMD + f] * W2[f];
    #pragma unroll
    for (int o = 16; o; o >>= 1) acc += __shfl_xor_sync(0xffffffffu, acc, o);
    if (lane == 0) {
        float sc = acc + b2[0];
        float lam = fmaxf(sc, 0.f) + log1pf(expf(-fabsf(sc)));
        if (full) dout[1 + warp] = lam;
        g_loss[warp] = -logf(lam + 1e-8f);
    }
}

__global__ void loss_reduce_kernel(float* __restrict__ dout)
{
    __shared__ float s[256];
    int tid = threadIdx.x;
    float a = 0.f;
    for (int i = tid; i < NEV; i += 256) a += g_loss[i];
    s[tid] = a;
    __syncthreads();
    for (int o = 128; o; o >>= 1) {
        if (tid < o) s[tid] += s[tid + o];
        __syncthreads();
    }
    if (tid == 0) dout[0] = s[0] / (float)NEV;
}

// ------------------------ final scatter into mem / latest_time ---------------
__global__ void scatter_kernel(const int* __restrict__ subj, const int* __restrict__ obj,
                               const float* __restrict__ tim,
                               float* __restrict__ outMem, float* __restrict__ outLt)
{
    int pos = blockIdx.x * 256 + threadIdx.x;
    if (pos >= NOCC || !g_isLast[pos]) return;
    int t = pos >> 6, r = pos & 63, ph = r >> 5, b = r & 31;
    int e = ph ? obj[b * TT + t] : subj[b * TT + t];
    int ev = t * 32 + b;
    const float* src = ph ? (g_newO + ev * DIMD) : (g_newS + ev * DIMD);
    float* dst = outMem + (size_t)e * DIMD;
    for (int f = 0; f < DIMD; f++) dst[f] = src[f];
    outLt[e] = tim[b * TT + t];
}

// ------------------------ launch ---------------------------------------------
extern "C" void kernel_launch(void* const* d_in, const int* in_sizes, int n_in,
                              void* d_out, int out_size)
{
    const int*   subj = (const int*)d_in[0];
    const int*   obj  = (const int*)d_in[1];
    const int*   rel  = (const int*)d_in[2];
    const float* tim  = (const float*)d_in[3];
    const float* mem  = (const float*)d_in[4];
    const float* lt   = (const float*)d_in[5];
    const float* remb = (const float*)d_in[6];
    const float* Wh   = (const float*)d_in[7];
    const float* Whh  = (const float*)d_in[8];
    const float* Wst  = (const float*)d_in[9];
    const float* Wot  = (const float*)d_in[10];
    const float* Wq   = (const float*)d_in[11];
    const float* Wk   = (const float*)d_in[12];
    const float* Wv   = (const float*)d_in[13];
    const float* Wo   = (const float*)d_in[14];
    const float* sW1  = (const float*)d_in[15];
    const float* sb1  = (const float*)d_in[16];
    const float* sW2  = (const float*)d_in[17];
    const float* sb2  = (const float*)d_in[18];
    float* dout = (float*)d_out;
    int full = (out_size >= OUT_FULL) ? 1 : 0;

    float *p_x, *p_e, *p_q, *p_k, *p_v, *p_ao, *p_s1, *p_inp, *p_h;
    cudaGetSymbolAddress((void**)&p_x,   g_x);
    cudaGetSymbolAddress((void**)&p_e,   g_e);
    cudaGetSymbolAddress((void**)&p_q,   g_q);
    cudaGetSymbolAddress((void**)&p_k,   g_k);
    cudaGetSymbolAddress((void**)&p_v,   g_v);
    cudaGetSymbolAddress((void**)&p_ao,  g_ao);
    cudaGetSymbolAddress((void**)&p_s1,  g_s1);
    cudaGetSymbolAddress((void**)&p_inp, g_inp);
    cudaGetSymbolAddress((void**)&p_h,   g_h);

    cudaFuncSetAttribute(attn_kernel, cudaFuncAttributeMaxDynamicSharedMemorySize, 81920);

    // ---- phase 1 ----
    links_kernel<<<16, 256>>>(subj, obj, tim, lt);
    depth_compact_kernel<<<1, 256>>>();
    gather0_kernel<<<(NEV * FEAT + 255) / 256, 256>>>(subj, obj, rel, mem, remb);
    // h = sigm(inp @ Wh): M=2048(limit), N=256, K=320
    mma_gen_kernel<<<dim3(4, 16), 256>>>(p_inp, FEAT, Wh, DIML, FEAT,
                                         p_h, DIML, FEAT, 3, nullptr, nullptr, 1);
    // dual-sigmoid: M=2048(limit), N=128, K=256
    mma_gen_kernel<<<dim3(2, 16), 256>>>(p_h, DIML, Whh, DIMD, DIML,
                                         p_h, DIMD, DIML, 4, Wst, Wot, 1);
    cleanup_kernel<<<16, 256>>>(subj, obj, rel, mem, remb, Wh, Whh, Wst, Wot);
    assemble_x_kernel<<<(NEV * FEAT + 255) / 256, 256>>>(rel, remb);

    // ---- phase 2 ----
    e_tail_kernel<<<(NEV * 144 + 255) / 256, 256>>>(tim);
    for (int l = 0; l < 2; l++) {
        const float* wq = Wq + (size_t)l * INDIM * FEAT;
        const float* wk = Wk + (size_t)l * INDIM * FEAT;
        const float* wv = Wv + (size_t)l * INDIM * FEAT;
        const float* wo = Wo + (size_t)l * FEAT * FEAT;
        qkv_mma_kernel<<<dim3(5, 16, 3), 256>>>(p_e, wq, wk, wv, p_q, p_k, p_v);
        attn_kernel<<<dim3(BB, NH), 256, 81920>>>();
        wo_mma_kernel<<<dim3(5, 16), 256>>>(p_ao, wo, p_x);
    }

    // ---- score head ----
    mma_gen_kernel<<<dim3(2, 16), 256>>>(p_x, FEAT, sW1, DIMD, FEAT,
                                         p_s1, DIMD, FEAT, 2, sb1, nullptr, 0);
    score2_kernel<<<(NEV * 32 + 255) / 256, 256>>>(sW2, sb2, dout, full);
    loss_reduce_kernel<<<1, 256>>>(dout);

    // ---- final mem / latest_time outputs ----
    if (full) {
        float* outMem = dout + 1 + NEV;
        float* outLt  = outMem + (size_t)200000 * DIMD;
        cudaMemcpyAsync(outMem, mem, (size_t)200000 * DIMD * sizeof(float),
                        cudaMemcpyDeviceToDevice, 0);
        cudaMemcpyAsync(outLt, lt, 200000 * sizeof(float),
                        cudaMemcpyDeviceToDevice, 0);
        scatter_kernel<<<16, 256>>>(subj, obj, tim, outMem, outLt);
    }
}

// round 14
// speedup vs baseline: 1.1076x; 1.1076x over previous
#include <cuda_runtime.h>
#include <cuda_bf16.h>
#include <math.h>
#include <stdint.h>

#define BB      32
#define TT      64
#define NEV     2048      // B*T events
#define NOCC    4096      // 2*B*T occurrences
#define DIMD    128
#define DIMC    64
#define DIML    256
#define FEAT    320
#define INDIM   449
#define ES      464       // padded e row stride (div by 16)
#define NH      4
#define DH      80
#define NWAVES  16
#define OUT_FULL 25802049  // 1 + 2048 + 200000*128 + 200000

// ------------------------ device scratch ------------------------------------
__device__ int   g_prevRead[NOCC];
__device__ int   g_isLast[NOCC];
__device__ int   g_depth[NEV];
__device__ int   g_order[NEV];
__device__ int   g_waveStart[NWAVES + 1];
__device__ int   g_bar[NWAVES];
__device__ float g_dts[NEV];
__device__ float g_dto[NEV];
__device__ float g_inp[NEV * FEAT];
__device__ float g_h[NEV * DIML];
__device__ float g_newS[NEV * DIMD];
__device__ float g_newO[NEV * DIMD];
__device__ float g_x[NEV * FEAT];
__device__ float g_e[NEV * ES + 64];
__device__ float g_q[NEV * FEAT];
__device__ float g_k[NEV * FEAT];
__device__ float g_v[NEV * FEAT];
__device__ float g_ao[NEV * FEAT];
__device__ float g_s1[NEV * DIMD];
__device__ float g_loss[NEV];

__device__ __forceinline__ float sigm(float x) { return 1.f / (1.f + expf(-x)); }

__device__ __forceinline__ uint32_t f2tf32(float f) {
    uint32_t u; asm("cvt.rna.tf32.f32 %0, %1;" : "=r"(u) : "f"(f)); return u;
}
__device__ __forceinline__ void mma_tf32(float* c, uint32_t a0, uint32_t a1,
                                         uint32_t a2, uint32_t a3,
                                         uint32_t b0, uint32_t b1) {
    asm volatile(
        "mma.sync.aligned.m16n8k8.row.col.f32.tf32.tf32.f32 "
        "{%0,%1,%2,%3}, {%4,%5,%6,%7}, {%8,%9}, {%0,%1,%2,%3};"
        : "+f"(c[0]), "+f"(c[1]), "+f"(c[2]), "+f"(c[3])
        : "r"(a0), "r"(a1), "r"(a2), "r"(a3), "r"(b0), "r"(b1));
}

// ------------------------ kernel A1: occurrence links -----------------------
__global__ void links_kernel(const int* __restrict__ subj, const int* __restrict__ obj,
                             const float* __restrict__ tim, const float* __restrict__ lt)
{
    __shared__ int s_ent[NOCC];
    int tid = threadIdx.x;
    for (int p = tid; p < NOCC; p += 256) {
        int t = p >> 6, r = p & 63, ph = r >> 5, b = r & 31;
        s_ent[p] = ph ? obj[b * TT + t] : subj[b * TT + t];
    }
    __syncthreads();
    int pos = blockIdx.x * 256 + tid;
    int e = s_ent[pos];
    int t = pos >> 6, r = pos & 63, ph = r >> 5, b = r & 31;
    int stepStart = t * 64;
    int prevR = -1, later = 0;
    for (int p2 = 0; p2 < NOCC; p2++) {
        if (s_ent[p2] == e) {
            if (p2 < stepStart) prevR = p2;
            if (p2 > pos) later = 1;
        }
    }
    g_prevRead[pos] = prevR;
    g_isLast[pos] = !later;
    float ltv = (prevR < 0) ? lt[e] : tim[(prevR & 31) * TT + (prevR >> 6)];
    float dt = tim[b * TT + t] - ltv;
    int ev = t * 32 + b;
    if (ph == 0) g_dts[ev] = dt; else g_dto[ev] = dt;
}

// ------------------------ kernel A2: depths + compaction ---------------------
__global__ void depth_compact_kernel()
{
    __shared__ int s_d[NEV];
    __shared__ int s_ps[NEV];
    __shared__ int s_po[NEV];
    __shared__ int s_cnt[NWAVES];
    __shared__ int s_off[NWAVES + 1];
    __shared__ int s_n;
    int tid = threadIdx.x;
    for (int ev = tid; ev < NEV; ev += 256) {
        int t = ev >> 5, b = ev & 31;
        int ps = g_prevRead[t * 64 + b];
        int po = g_prevRead[t * 64 + 32 + b];
        s_ps[ev] = (ps < 0) ? -1 : ((ps >> 6) * 32 + (ps & 31));
        s_po[ev] = (po < 0) ? -1 : ((po >> 6) * 32 + (po & 31));
        s_d[ev] = -1;
    }
    if (tid < NWAVES) { s_cnt[tid] = 0; g_bar[tid] = 0; }
    if (tid == 0) s_n = 0;
    __syncthreads();
    for (int pass = 0; pass < 32; pass++) {
        for (int ev = tid; ev < NEV; ev += 256) {
            if (s_d[ev] < 0) {
                int a = s_ps[ev], b2 = s_po[ev];
                int da = (a < 0) ? -1 : s_d[a];
                int db = (b2 < 0) ? -1 : s_d[b2];
                bool ra = (a < 0) || (da >= 0);
                bool rb = (b2 < 0) || (db >= 0);
                if (ra && rb) { s_d[ev] = max(da, db) + 1; atomicAdd(&s_n, 1); }
            }
        }
        __syncthreads();
        if (s_n >= NEV) break;
    }
    for (int ev = tid; ev < NEV; ev += 256) {
        int d = s_d[ev];
        d = (d < 0) ? 0 : ((d > NWAVES - 1) ? NWAVES - 1 : d);
        s_d[ev] = d;
        g_depth[ev] = d;
        atomicAdd(&s_cnt[d], 1);
    }
    __syncthreads();
    if (tid == 0) {
        int acc = 0;
        for (int w = 0; w < NWAVES; w++) { s_off[w] = acc; acc += s_cnt[w]; }
        s_off[NWAVES] = acc;
        for (int w = 0; w <= NWAVES; w++) g_waveStart[w] = s_off[w];
        for (int w = 0; w < NWAVES; w++) s_cnt[w] = s_off[w];
    }
    __syncthreads();
    for (int ev = tid; ev < NEV; ev += 256) {
        int pos = atomicAdd(&s_cnt[s_d[ev]], 1);
        g_order[pos] = ev;
    }
}

// ------------------------ gather wave-0 inputs -------------------------------
__global__ void gather0_kernel(const int* __restrict__ subj, const int* __restrict__ obj,
                               const int* __restrict__ rel,
                               const float* __restrict__ mem, const float* __restrict__ remb)
{
    int idx = blockIdx.x * 256 + threadIdx.x;
    if (idx >= NEV * FEAT) return;
    int row = idx / FEAT, f = idx - row * FEAT;
    if (row >= g_waveStart[1]) return;
    int ev = g_order[row];
    int t = ev >> 5, b = ev & 31;
    float val;
    if (f < 256) {
        int which = f >> 7, ff = f & 127;
        int ent = which ? obj[b * TT + t] : subj[b * TT + t];
        val = mem[(size_t)ent * DIMD + ff];
    } else {
        val = remb[rel[b * TT + t] * DIMC + (f - 256)];
    }
    g_inp[row * FEAT + f] = val;
}

// ------------------------ tf32 tensor-core GEMM (128x64 tile) ----------------
// Register-prefetch of next k-tile overlaps LDG latency with mma phase.
// epi: 0 store; 5: C += tanh(acc) AND mirror into g_e
__device__ __forceinline__ void mma128_body(
    const float* __restrict__ A, int lda,
    const float* __restrict__ Bm, int ldb, int Kb,
    float* __restrict__ C, int ldc, int K, int epi)
{
    __shared__ uint32_t As[16][136];   // [k][m], stride 136 -> conflict-free frags
    __shared__ uint32_t Bs2[16][68];   // [k][(n%8)*8 + n/8]
    int tid = threadIdx.x;
    int lane = tid & 31, warp = tid >> 5;
    int tg = lane & 3, gid = lane >> 2;
    int row0 = blockIdx.y * 128;
    int col0 = blockIdx.x * 64;
    int mw = warp * 16;
    int gid8 = gid * 8;

    float acc[8][4];
    #pragma unroll
    for (int j = 0; j < 8; j++)
        #pragma unroll
        for (int c = 0; c < 4; c++) acc[j][c] = 0.f;

    int arow = tid >> 1;            // 0..127
    int akoff = (tid & 1) * 8;      // 0 or 8
    int bk = tid >> 4;              // 0..15
    int bn = (tid & 15) * 4;        // 0..60

    const float* aptr = A + (size_t)(row0 + arow) * lda + akoff;
    const float* bptr = Bm + (size_t)bk * ldb + col0 + bn;

    // prologue: prefetch tile kt=0
    float4 av0 = *(const float4*)(aptr);
    float4 av1 = *(const float4*)(aptr + 4);
    float4 bv = (bk < Kb) ? *(const float4*)(bptr) : make_float4(0.f, 0.f, 0.f, 0.f);

    for (int kt = 0; kt < K; kt += 16) {
        // store prefetched tile (with tf32 convert)
        As[akoff + 0][arow] = f2tf32(av0.x);
        As[akoff + 1][arow] = f2tf32(av0.y);
        As[akoff + 2][arow] = f2tf32(av0.z);
        As[akoff + 3][arow] = f2tf32(av0.w);
        As[akoff + 4][arow] = f2tf32(av1.x);
        As[akoff + 5][arow] = f2tf32(av1.y);
        As[akoff + 6][arow] = f2tf32(av1.z);
        As[akoff + 7][arow] = f2tf32(av1.w);
        Bs2[bk][((bn + 0) & 7) * 8 + ((bn + 0) >> 3)] = f2tf32(bv.x);
        Bs2[bk][((bn + 1) & 7) * 8 + ((bn + 1) >> 3)] = f2tf32(bv.y);
        Bs2[bk][((bn + 2) & 7) * 8 + ((bn + 2) >> 3)] = f2tf32(bv.z);
        Bs2[bk][((bn + 3) & 7) * 8 + ((bn + 3) >> 3)] = f2tf32(bv.w);
        __syncthreads();
        // prefetch next tile (LDG latency hides under the mma phase)
        int kn = kt + 16;
        if (kn < K) {
            av0 = *(const float4*)(aptr + kn);
            av1 = *(const float4*)(aptr + kn + 4);
            int gk = kn + bk;
            bv = (gk < Kb) ? *(const float4*)(bptr + (size_t)kn * ldb)
                           : make_float4(0.f, 0.f, 0.f, 0.f);
        }
        #pragma unroll
        for (int ks = 0; ks < 16; ks += 8) {
            uint32_t a0 = As[ks + tg][mw + gid];
            uint32_t a1 = As[ks + tg][mw + gid + 8];
            uint32_t a2 = As[ks + tg + 4][mw + gid];
            uint32_t a3 = As[ks + tg + 4][mw + gid + 8];
            uint4 B0a = *(const uint4*)&Bs2[ks + tg][gid8];
            uint4 B0b = *(const uint4*)&Bs2[ks + tg][gid8 + 4];
            uint4 B1a = *(const uint4*)&Bs2[ks + tg + 4][gid8];
            uint4 B1b = *(const uint4*)&Bs2[ks + tg + 4][gid8 + 4];
            mma_tf32(acc[0], a0, a1, a2, a3, B0a.x, B1a.x);
            mma_tf32(acc[1], a0, a1, a2, a3, B0a.y, B1a.y);
            mma_tf32(acc[2], a0, a1, a2, a3, B0a.z, B1a.z);
            mma_tf32(acc[3], a0, a1, a2, a3, B0a.w, B1a.w);
            mma_tf32(acc[4], a0, a1, a2, a3, B0b.x, B1b.x);
            mma_tf32(acc[5], a0, a1, a2, a3, B0b.y, B1b.y);
            mma_tf32(acc[6], a0, a1, a2, a3, B0b.z, B1b.z);
            mma_tf32(acc[7], a0, a1, a2, a3, B0b.w, B1b.w);
        }
        __syncthreads();
    }

    #pragma unroll
    for (int j = 0; j < 8; j++) {
        int cc = col0 + j * 8 + tg * 2;
        int r0 = row0 + mw + gid;
        int r1 = r0 + 8;
        if (epi == 0) {
            *(float2*)&C[(size_t)r0 * ldc + cc] = make_float2(acc[j][0], acc[j][1]);
            *(float2*)&C[(size_t)r1 * ldc + cc] = make_float2(acc[j][2], acc[j][3]);
        } else {   // epi 5
            float n0 = C[(size_t)r0 * ldc + cc]     + tanhf(acc[j][0]);
            float n1 = C[(size_t)r0 * ldc + cc + 1] + tanhf(acc[j][1]);
            float n2 = C[(size_t)r1 * ldc + cc]     + tanhf(acc[j][2]);
            float n3 = C[(size_t)r1 * ldc + cc + 1] + tanhf(acc[j][3]);
            C[(size_t)r0 * ldc + cc]     = n0;  g_e[(size_t)r0 * ES + cc]     = n0;
            C[(size_t)r0 * ldc + cc + 1] = n1;  g_e[(size_t)r0 * ES + cc + 1] = n1;
            C[(size_t)r1 * ldc + cc]     = n2;  g_e[(size_t)r1 * ES + cc]     = n2;
            C[(size_t)r1 * ldc + cc + 1] = n3;  g_e[(size_t)r1 * ES + cc + 1] = n3;
        }
    }
}

__global__ void __launch_bounds__(256) qkv_mma_kernel(
    const float* __restrict__ A,
    const float* __restrict__ B0, const float* __restrict__ B1, const float* __restrict__ B2,
    float* __restrict__ C0, float* __restrict__ C1, float* __restrict__ C2)
{
    const float* Bm = (blockIdx.z == 0) ? B0 : (blockIdx.z == 1) ? B1 : B2;
    float* C = (blockIdx.z == 0) ? C0 : (blockIdx.z == 1) ? C1 : C2;
    mma128_body(A, ES, Bm, FEAT, INDIM, C, FEAT, ES, 0);
}

__global__ void __launch_bounds__(256) wo_mma_kernel(
    const float* __restrict__ A, const float* __restrict__ Bm, float* __restrict__ C)
{
    mma128_body(A, FEAT, Bm, FEAT, FEAT, C, FEAT, FEAT, 5);
}

// ------------------------ 32x32-tile fp32 GEMM (occupancy variant) -----------
__global__ void __launch_bounds__(256) gemm32_kernel(
    const float* __restrict__ A, int lda, const float* __restrict__ Bm, int ldb,
    float* __restrict__ C, int ldc, int K, int epi,
    const float* __restrict__ bias, const float* __restrict__ bias2, int useLimit)
{
    int limit = useLimit ? g_waveStart[1] : NEV;
    __shared__ float As[16][36];
    __shared__ float Bs[16][36];
    int tid = threadIdx.x;
    int tx = tid & 15, ty = tid >> 4;
    int row0 = blockIdx.y * 32;
    int col0 = blockIdx.x * 32;
    if (row0 >= limit) return;
    float acc[2][2] = {{0.f, 0.f}, {0.f, 0.f}};

    int am = tid >> 3;
    int ak = (tid & 7) * 2;
    int bk = tid >> 4;
    int bn = (tid & 15) * 2;

    for (int kt = 0; kt < K; kt += 16) {
        float2 av = *(const float2*)(A + (size_t)(row0 + am) * lda + kt + ak);
        As[ak + 0][am] = av.x; As[ak + 1][am] = av.y;
        float2 bv = *(const float2*)(Bm + (size_t)(kt + bk) * ldb + col0 + bn);
        Bs[bk][bn + 0] = bv.x; Bs[bk][bn + 1] = bv.y;
        __syncthreads();
        #pragma unroll
        for (int kk = 0; kk < 16; kk++) {
            float2 a = *(const float2*)&As[kk][ty * 2];
            float2 b = *(const float2*)&Bs[kk][tx * 2];
            acc[0][0] += a.x * b.x; acc[0][1] += a.x * b.y;
            acc[1][0] += a.y * b.x; acc[1][1] += a.y * b.y;
        }
        __syncthreads();
    }
    #pragma unroll
    for (int r = 0; r < 2; r++) {
        int rr = row0 + ty * 2 + r;
        if (rr >= limit) continue;
        #pragma unroll
        for (int c = 0; c < 2; c++) {
            int cc = col0 + tx * 2 + c;
            float v = acc[r][c];
            if (epi == 0)      C[(size_t)rr * ldc + cc] = v;
            else if (epi == 2) C[(size_t)rr * ldc + cc] = fmaxf(v + bias[cc], 0.f);
            else if (epi == 3) C[(size_t)rr * ldc + cc] = sigm(v);
            else if (epi == 4) {
                int ev = g_order[rr];
                g_newS[ev * DIMD + cc] = sigm(g_dts[ev] * bias[cc]  + v);
                g_newO[ev * DIMD + cc] = sigm(g_dto[ev] * bias2[cc] + v);
            }
        }
    }
}

// ------------------------ cleanup: waves >= 1 (persistent, 16 blocks) --------
__global__ void __launch_bounds__(256) cleanup_kernel(
    const int* __restrict__ subj, const int* __restrict__ obj,
    const int* __restrict__ rel,
    const float* __restrict__ mem, const float* __restrict__ remb,
    const float* __restrict__ Wh, const float* __restrict__ Whh,
    const float* __restrict__ Wst, const float* __restrict__ Wot)
{
    __shared__ float s_inp[FEAT];
    __shared__ float s_h[DIML];
    int tid = threadIdx.x;
    for (int w = 1; w < NWAVES; w++) {
        int ws = g_waveStart[w], we = g_waveStart[w + 1];
        if (ws >= NEV) break;
        for (int i = ws + blockIdx.x; i < we; i += 16) {
            int ev = g_order[i];
            int t = ev >> 5, b = ev & 31;
            for (int f = tid; f < FEAT; f += 256) {
                float val;
                if (f < 256) {
                    int which = f >> 7, ff = f & 127;
                    int pred = g_prevRead[t * 64 + which * 32 + b];
                    if (pred < 0) {
                        int ent = which ? obj[b * TT + t] : subj[b * TT + t];
                        val = mem[(size_t)ent * DIMD + ff];
                    } else {
                        int pph = (pred >> 5) & 1;
                        int pev = (pred >> 6) * 32 + (pred & 31);
                        val = pph ? g_newO[pev * DIMD + ff] : g_newS[pev * DIMD + ff];
                    }
                } else {
                    val = remb[rel[b * TT + t] * DIMC + (f - 256)];
                }
                s_inp[f] = val;
            }
            __syncthreads();
            {
                float acc = 0.f;
                #pragma unroll 4
                for (int k = 0; k < FEAT; k++)
                    acc += s_inp[k] * Wh[(size_t)k * DIML + tid];
                s_h[tid] = sigm(acc);
            }
            __syncthreads();
            if (tid < DIMD) {
                float acc = 0.f;
                #pragma unroll 4
                for (int k = 0; k < DIML; k++)
                    acc += s_h[k] * Whh[(size_t)k * DIMD + tid];
                g_newS[ev * DIMD + tid] = sigm(g_dts[ev] * Wst[tid] + acc);
                g_newO[ev * DIMD + tid] = sigm(g_dto[ev] * Wot[tid] + acc);
            }
            __syncthreads();
        }
        __threadfence();
        __syncthreads();
        if (tid == 0) {
            atomicAdd(&g_bar[w], 1);
            while (atomicAdd(&g_bar[w], 0) < 16) { }
        }
        __syncthreads();
        __threadfence();
    }
}

// ------------------------ assemble evt rows (writes g_x AND g_e) -------------
__global__ void assemble_x_kernel(const int* __restrict__ rel,
                                  const float* __restrict__ remb)
{
    int idx = blockIdx.x * 256 + threadIdx.x;
    if (idx >= NEV * FEAT) return;
    int row = idx / FEAT, f = idx - row * FEAT;
    int b = row >> 6, t = row & 63;
    int ev = t * 32 + b;
    float val;
    if (f < 128)      val = g_newS[ev * DIMD + f];
    else if (f < 256) val = g_newO[ev * DIMD + (f - 128)];
    else              val = remb[rel[row] * DIMC + (f - 256)];
    g_x[idx] = val;
    g_e[(size_t)row * ES + f] = val;
}

// e tail cols: [320..448)=sin(time*norm), 448=1, 449..463=0  (written once)
__global__ void e_tail_kernel(const float* __restrict__ tim)
{
    int idx = blockIdx.x * 256 + threadIdx.x;
    int row = idx / 144, f = idx - row * 144;
    if (row >= NEV) return;
    int col = FEAT + f;
    float val;
    if (f < DIMD) {
        float p = powf(10000.0f, (float)f);
        float nrm = isinf(p) ? 0.0f : (1.0f / p);
        val = sinf(tim[row] * nrm);
    } else if (col == INDIM - 1) val = 1.0f;
    else val = 0.0f;
    g_e[(size_t)row * ES + col] = val;
}

// ------------------------ attention (per b,h block) --------------------------
__global__ void __launch_bounds__(256) attn_kernel()
{
    extern __shared__ float sm[];
    float* sq = sm;
    float* sk = sq + 64 * 84;
    float* sv = sk + 64 * 84;
    float* ssc = sv + 64 * 84;
    int b = blockIdx.x, h = blockIdx.y;
    int tid = threadIdx.x;
    const float scale = 0.111803398875f;

    for (int idx = tid; idx < 64 * DH; idx += 256) {
        int i = idx / DH, d = idx - i * DH;
        int row = b * TT + i, col = h * DH + d;
        sq[i * 84 + d] = g_q[(size_t)row * FEAT + col];
        sk[i * 84 + d] = g_k[(size_t)row * FEAT + col];
        sv[i * 84 + d] = g_v[(size_t)row * FEAT + col];
    }
    __syncthreads();
    {
        int i = tid >> 2, jg = tid & 3;
        float acc[16];
        #pragma unroll
        for (int jj = 0; jj < 16; jj++) acc[jj] = 0.f;
        for (int kk = 0; kk < 20; kk++) {
            float4 qv = *(const float4*)&sq[i * 84 + kk * 4];
            #pragma unroll
            for (int jj = 0; jj < 16; jj++) {
                int j = jg * 16 + jj;
                float4 kv = *(const float4*)&sk[j * 84 + kk * 4];
                acc[jj] += qv.x * kv.x + qv.y * kv.y + qv.z * kv.z + qv.w * kv.w;
            }
        }
        #pragma unroll
        for (int jj = 0; jj < 16; jj++)
            ssc[i * 68 + jg * 16 + jj] = acc[jj] * scale;
    }
    __syncthreads();
    if (tid < 64) {
        int i = tid;
        if (i == 0) {
            for (int j = 0; j < 64; j++) ssc[j] = 0.f;
        } else {
            float mx = -1e30f;
            for (int j = 0; j < i; j++) mx = fmaxf(mx, ssc[i * 68 + j]);
            float sum = 0.f;
            for (int j = 0; j < i; j++) sum += expf(ssc[i * 68 + j] - mx);
            float inv = 1.f / sum;
            for (int j = 0; j < i; j++) ssc[i * 68 + j] = expf(ssc[i * 68 + j] - mx) * inv;
            for (int j = i; j < 64; j++) ssc[i * 68 + j] = 0.f;
        }
    }
    __syncthreads();
    {
        int i = tid >> 2, dg = tid & 3, d0 = dg * 20;
        float acc[20];
        #pragma unroll
        for (int dd = 0; dd < 20; dd++) acc[dd] = 0.f;
        for (int j = 0; j < 64; j++) {
            float a = ssc[i * 68 + j];
            #pragma unroll
            for (int dd = 0; dd < 20; dd++)
                acc[dd] += a * sv[j * 84 + d0 + dd];
        }
        int row = b * TT + i;
        #pragma unroll
        for (int dd = 0; dd < 20; dd++)
            g_ao[(size_t)row * FEAT + h * DH + d0 + dd] = acc[dd];
    }
}

// ------------------------ score head + loss (fused) --------------------------
__global__ void score2_loss_kernel(const float* __restrict__ W2, const float* __restrict__ b2,
                                   float* __restrict__ dout, int full)
{
    // 256 blocks x 256 threads: 8 events per block
    __shared__ float s_part[8];
    int tid = threadIdx.x;
    int warp = tid >> 5, lane = tid & 31;
    int ev = blockIdx.x * 8 + warp;
    float acc = 0.f;
    for (int f = lane; f < DIMD; f += 32)
        acc += g_s1[ev * DIMD + f] * W2[f];
    #pragma unroll
    for (int o = 16; o; o >>= 1) acc += __shfl_xor_sync(0xffffffffu, acc, o);
    if (lane == 0) {
        float sc = acc + b2[0];
        float lam = fmaxf(sc, 0.f) + log1pf(expf(-fabsf(sc)));
        if (full) dout[1 + ev] = lam;
        g_loss[ev] = -logf(lam + 1e-8f);
        s_part[warp] = 0.f;   // placeholder (loss reduced separately)
    }
    (void)s_part;
}

__global__ void loss_reduce_kernel(float* __restrict__ dout)
{
    __shared__ float s[256];
    int tid = threadIdx.x;
    float a = 0.f;
    for (int i = tid; i < NEV; i += 256) a += g_loss[i];
    s[tid] = a;
    __syncthreads();
    for (int o = 128; o; o >>= 1) {
        if (tid < o) s[tid] += s[tid + o];
        __syncthreads();
    }
    if (tid == 0) dout[0] = s[0] / (float)NEV;
}

// ------------------------ final scatter into mem / latest_time ---------------
__global__ void scatter_kernel(const int* __restrict__ subj, const int* __restrict__ obj,
                               const float* __restrict__ tim,
                               float* __restrict__ outMem, float* __restrict__ outLt)
{
    int pos = blockIdx.x * 256 + threadIdx.x;
    if (pos >= NOCC || !g_isLast[pos]) return;
    int t = pos >> 6, r = pos & 63, ph = r >> 5, b = r & 31;
    int e = ph ? obj[b * TT + t] : subj[b * TT + t];
    int ev = t * 32 + b;
    const float* src = ph ? (g_newO + ev * DIMD) : (g_newS + ev * DIMD);
    float* dst = outMem + (size_t)e * DIMD;
    for (int f = 0; f < DIMD; f++) dst[f] = src[f];
    outLt[e] = tim[b * TT + t];
}

// ------------------------ launch ---------------------------------------------
extern "C" void kernel_launch(void* const* d_in, const int* in_sizes, int n_in,
                              void* d_out, int out_size)
{
    const int*   subj = (const int*)d_in[0];
    const int*   obj  = (const int*)d_in[1];
    const int*   rel  = (const int*)d_in[2];
    const float* tim  = (const float*)d_in[3];
    const float* mem  = (const float*)d_in[4];
    const float* lt   = (const float*)d_in[5];
    const float* remb = (const float*)d_in[6];
    const float* Wh   = (const float*)d_in[7];
    const float* Whh  = (const float*)d_in[8];
    const float* Wst  = (const float*)d_in[9];
    const float* Wot  = (const float*)d_in[10];
    const float* Wq   = (const float*)d_in[11];
    const float* Wk   = (const float*)d_in[12];
    const float* Wv   = (const float*)d_in[13];
    const float* Wo   = (const float*)d_in[14];
    const float* sW1  = (const float*)d_in[15];
    const float* sb1  = (const float*)d_in[16];
    const float* sW2  = (const float*)d_in[17];
    const float* sb2  = (const float*)d_in[18];
    float* dout = (float*)d_out;
    int full = (out_size >= OUT_FULL) ? 1 : 0;

    float *p_x, *p_e, *p_q, *p_k, *p_v, *p_ao, *p_s1, *p_inp, *p_h;
    cudaGetSymbolAddress((void**)&p_x,   g_x);
    cudaGetSymbolAddress((void**)&p_e,   g_e);
    cudaGetSymbolAddress((void**)&p_q,   g_q);
    cudaGetSymbolAddress((void**)&p_k,   g_k);
    cudaGetSymbolAddress((void**)&p_v,   g_v);
    cudaGetSymbolAddress((void**)&p_ao,  g_ao);
    cudaGetSymbolAddress((void**)&p_s1,  g_s1);
    cudaGetSymbolAddress((void**)&p_inp, g_inp);
    cudaGetSymbolAddress((void**)&p_h,   g_h);

    cudaFuncSetAttribute(attn_kernel, cudaFuncAttributeMaxDynamicSharedMemorySize, 81920);

    // ---- phase 1 ----
    links_kernel<<<16, 256>>>(subj, obj, tim, lt);
    depth_compact_kernel<<<1, 256>>>();
    gather0_kernel<<<(NEV * FEAT + 255) / 256, 256>>>(subj, obj, rel, mem, remb);
    gemm32_kernel<<<dim3(8, 64), 256>>>(p_inp, FEAT, Wh, DIML, p_h, DIML,
                                        FEAT, 3, nullptr, nullptr, 1);
    gemm32_kernel<<<dim3(4, 64), 256>>>(p_h, DIML, Whh, DIMD, p_h /*unused*/, DIMD,
                                        DIML, 4, Wst, Wot, 1);
    cleanup_kernel<<<16, 256>>>(subj, obj, rel, mem, remb, Wh, Whh, Wst, Wot);
    assemble_x_kernel<<<(NEV * FEAT + 255) / 256, 256>>>(rel, remb);

    // ---- phase 2 ----
    e_tail_kernel<<<(NEV * 144 + 255) / 256, 256>>>(tim);
    for (int l = 0; l < 2; l++) {
        const float* wq = Wq + (size_t)l * INDIM * FEAT;
        const float* wk = Wk + (size_t)l * INDIM * FEAT;
        const float* wv = Wv + (size_t)l * INDIM * FEAT;
        const float* wo = Wo + (size_t)l * FEAT * FEAT;
        qkv_mma_kernel<<<dim3(5, 16, 3), 256>>>(p_e, wq, wk, wv, p_q, p_k, p_v);
        attn_kernel<<<dim3(BB, NH), 256, 81920>>>();
        wo_mma_kernel<<<dim3(5, 16), 256>>>(p_ao, wo, p_x);
    }

    // ---- score head (fp32 for accuracy) ----
    gemm32_kernel<<<dim3(4, 64), 256>>>(p_x, FEAT, sW1, DIMD, p_s1, DIMD,
                                        FEAT, 2, sb1, nullptr, 0);
    score2_loss_kernel<<<NEV / 8, 256>>>(sW2, sb2, dout, full);
    loss_reduce_kernel<<<1, 256>>>(dout);

    // ---- final mem / latest_time outputs ----
    if (full) {
        float* outMem = dout + 1 + NEV;
        float* outLt  = outMem + (size_t)200000 * DIMD;
        cudaMemcpyAsync(outMem, mem, (size_t)200000 * DIMD * sizeof(float),
                        cudaMemcpyDeviceToDevice, 0);
        cudaMemcpyAsync(outLt, lt, 200000 * sizeof(float),
                        cudaMemcpyDeviceToDevice, 0);
        scatter_kernel<<<16, 256>>>(subj, obj, tim, outMem, outLt);
    }
}

// round 15
// speedup vs baseline: 1.1179x; 1.0093x over previous
#include <cuda_runtime.h>
#include <cuda_bf16.h>
#include <math.h>
#include <stdint.h>

#define BB      32
#define TT      64
#define NEV     2048      // B*T events
#define NOCC    4096      // 2*B*T occurrences
#define DIMD    128
#define DIMC    64
#define DIML    256
#define FEAT    320
#define INDIM   449
#define ES      464       // padded e row stride (div by 16)
#define NH      4
#define DH      80
#define NWAVES  16
#define OUT_FULL 25802049  // 1 + 2048 + 200000*128 + 200000

// ------------------------ device scratch ------------------------------------
__device__ int   g_prevRead[NOCC];
__device__ int   g_isLast[NOCC];
__device__ int   g_depth[NEV];
__device__ int   g_order[NEV];
__device__ int   g_waveStart[NWAVES + 1];
__device__ int   g_bar[NWAVES];
__device__ float g_dts[NEV];
__device__ float g_dto[NEV];
__device__ float g_inp[NEV * FEAT];
__device__ float g_h[NEV * DIML];
__device__ float g_newS[NEV * DIMD];
__device__ float g_newO[NEV * DIMD];
__device__ float g_x[NEV * FEAT];
__device__ float g_e[NEV * ES + 64];
__device__ float g_q[NEV * FEAT];
__device__ float g_k[NEV * FEAT];
__device__ float g_v[NEV * FEAT];
__device__ float g_ao[NEV * FEAT];
__device__ float g_s1[NEV * DIMD];
__device__ float g_loss[NEV];

__device__ __forceinline__ float sigm(float x) { return 1.f / (1.f + expf(-x)); }

__device__ __forceinline__ uint32_t f2tf32(float f) {
    uint32_t u; asm("cvt.rna.tf32.f32 %0, %1;" : "=r"(u) : "f"(f)); return u;
}
__device__ __forceinline__ void mma_tf32(float* c, uint32_t a0, uint32_t a1,
                                         uint32_t a2, uint32_t a3,
                                         uint32_t b0, uint32_t b1) {
    asm volatile(
        "mma.sync.aligned.m16n8k8.row.col.f32.tf32.tf32.f32 "
        "{%0,%1,%2,%3}, {%4,%5,%6,%7}, {%8,%9}, {%0,%1,%2,%3};"
        : "+f"(c[0]), "+f"(c[1]), "+f"(c[2]), "+f"(c[3])
        : "r"(a0), "r"(a1), "r"(a2), "r"(a3), "r"(b0), "r"(b1));
}

// ------------------------ kernel A1: occurrence links -----------------------
__global__ void links_kernel(const int* __restrict__ subj, const int* __restrict__ obj,
                             const float* __restrict__ tim, const float* __restrict__ lt)
{
    __shared__ int s_ent[NOCC];
    int tid = threadIdx.x;
    for (int p = tid; p < NOCC; p += 256) {
        int t = p >> 6, r = p & 63, ph = r >> 5, b = r & 31;
        s_ent[p] = ph ? obj[b * TT + t] : subj[b * TT + t];
    }
    __syncthreads();
    int pos = blockIdx.x * 256 + tid;
    int e = s_ent[pos];
    int t = pos >> 6, r = pos & 63, ph = r >> 5, b = r & 31;
    int stepStart = t * 64;
    int prevR = -1, later = 0;
    for (int p2 = 0; p2 < NOCC; p2++) {
        if (s_ent[p2] == e) {
            if (p2 < stepStart) prevR = p2;
            if (p2 > pos) later = 1;
        }
    }
    g_prevRead[pos] = prevR;
    g_isLast[pos] = !later;
    float ltv = (prevR < 0) ? lt[e] : tim[(prevR & 31) * TT + (prevR >> 6)];
    float dt = tim[b * TT + t] - ltv;
    int ev = t * 32 + b;
    if (ph == 0) g_dts[ev] = dt; else g_dto[ev] = dt;
}

// ------------------------ kernel A2: depths + compaction ---------------------
__global__ void depth_compact_kernel()
{
    __shared__ int s_d[NEV];
    __shared__ int s_ps[NEV];
    __shared__ int s_po[NEV];
    __shared__ int s_cnt[NWAVES];
    __shared__ int s_off[NWAVES + 1];
    __shared__ int s_n;
    int tid = threadIdx.x;
    for (int ev = tid; ev < NEV; ev += 256) {
        int t = ev >> 5, b = ev & 31;
        int ps = g_prevRead[t * 64 + b];
        int po = g_prevRead[t * 64 + 32 + b];
        s_ps[ev] = (ps < 0) ? -1 : ((ps >> 6) * 32 + (ps & 31));
        s_po[ev] = (po < 0) ? -1 : ((po >> 6) * 32 + (po & 31));
        s_d[ev] = -1;
    }
    if (tid < NWAVES) { s_cnt[tid] = 0; g_bar[tid] = 0; }
    if (tid == 0) s_n = 0;
    __syncthreads();
    for (int pass = 0; pass < 32; pass++) {
        for (int ev = tid; ev < NEV; ev += 256) {
            if (s_d[ev] < 0) {
                int a = s_ps[ev], b2 = s_po[ev];
                int da = (a < 0) ? -1 : s_d[a];
                int db = (b2 < 0) ? -1 : s_d[b2];
                bool ra = (a < 0) || (da >= 0);
                bool rb = (b2 < 0) || (db >= 0);
                if (ra && rb) { s_d[ev] = max(da, db) + 1; atomicAdd(&s_n, 1); }
            }
        }
        __syncthreads();
        if (s_n >= NEV) break;
    }
    for (int ev = tid; ev < NEV; ev += 256) {
        int d = s_d[ev];
        d = (d < 0) ? 0 : ((d > NWAVES - 1) ? NWAVES - 1 : d);
        s_d[ev] = d;
        g_depth[ev] = d;
        atomicAdd(&s_cnt[d], 1);
    }
    __syncthreads();
    if (tid == 0) {
        int acc = 0;
        for (int w = 0; w < NWAVES; w++) { s_off[w] = acc; acc += s_cnt[w]; }
        s_off[NWAVES] = acc;
        for (int w = 0; w <= NWAVES; w++) g_waveStart[w] = s_off[w];
        for (int w = 0; w < NWAVES; w++) s_cnt[w] = s_off[w];
    }
    __syncthreads();
    for (int ev = tid; ev < NEV; ev += 256) {
        int pos = atomicAdd(&s_cnt[s_d[ev]], 1);
        g_order[pos] = ev;
    }
}

// ------------------------ gather wave-0 inputs -------------------------------
__global__ void gather0_kernel(const int* __restrict__ subj, const int* __restrict__ obj,
                               const int* __restrict__ rel,
                               const float* __restrict__ mem, const float* __restrict__ remb)
{
    int idx = blockIdx.x * 256 + threadIdx.x;
    if (idx >= NEV * FEAT) return;
    int row = idx / FEAT, f = idx - row * FEAT;
    if (row >= g_waveStart[1]) return;
    int ev = g_order[row];
    int t = ev >> 5, b = ev & 31;
    float val;
    if (f < 256) {
        int which = f >> 7, ff = f & 127;
        int ent = which ? obj[b * TT + t] : subj[b * TT + t];
        val = mem[(size_t)ent * DIMD + ff];
    } else {
        val = remb[rel[b * TT + t] * DIMC + (f - 256)];
    }
    g_inp[row * FEAT + f] = val;
}

// ------------------------ tf32 tensor-core GEMM (128x64 tile) ----------------
// Register-prefetch of next k-tile overlaps LDG latency with mma phase.
// epi: 0 store; 5: C += tanh(acc) AND mirror into g_e
__device__ __forceinline__ void mma128_body(
    const float* __restrict__ A, int lda,
    const float* __restrict__ Bm, int ldb, int Kb,
    float* __restrict__ C, int ldc, int K, int epi)
{
    __shared__ uint32_t As[16][136];
    __shared__ uint32_t Bs2[16][68];
    int tid = threadIdx.x;
    int lane = tid & 31, warp = tid >> 5;
    int tg = lane & 3, gid = lane >> 2;
    int row0 = blockIdx.y * 128;
    int col0 = blockIdx.x * 64;
    int mw = warp * 16;
    int gid8 = gid * 8;

    float acc[8][4];
    #pragma unroll
    for (int j = 0; j < 8; j++)
        #pragma unroll
        for (int c = 0; c < 4; c++) acc[j][c] = 0.f;

    int arow = tid >> 1;
    int akoff = (tid & 1) * 8;
    int bk = tid >> 4;
    int bn = (tid & 15) * 4;

    const float* aptr = A + (size_t)(row0 + arow) * lda + akoff;
    const float* bptr = Bm + (size_t)bk * ldb + col0 + bn;

    float4 av0 = *(const float4*)(aptr);
    float4 av1 = *(const float4*)(aptr + 4);
    float4 bv = (bk < Kb) ? *(const float4*)(bptr) : make_float4(0.f, 0.f, 0.f, 0.f);

    for (int kt = 0; kt < K; kt += 16) {
        As[akoff + 0][arow] = f2tf32(av0.x);
        As[akoff + 1][arow] = f2tf32(av0.y);
        As[akoff + 2][arow] = f2tf32(av0.z);
        As[akoff + 3][arow] = f2tf32(av0.w);
        As[akoff + 4][arow] = f2tf32(av1.x);
        As[akoff + 5][arow] = f2tf32(av1.y);
        As[akoff + 6][arow] = f2tf32(av1.z);
        As[akoff + 7][arow] = f2tf32(av1.w);
        Bs2[bk][((bn + 0) & 7) * 8 + ((bn + 0) >> 3)] = f2tf32(bv.x);
        Bs2[bk][((bn + 1) & 7) * 8 + ((bn + 1) >> 3)] = f2tf32(bv.y);
        Bs2[bk][((bn + 2) & 7) * 8 + ((bn + 2) >> 3)] = f2tf32(bv.z);
        Bs2[bk][((bn + 3) & 7) * 8 + ((bn + 3) >> 3)] = f2tf32(bv.w);
        __syncthreads();
        int kn = kt + 16;
        if (kn < K) {
            av0 = *(const float4*)(aptr + kn);
            av1 = *(const float4*)(aptr + kn + 4);
            int gk = kn + bk;
            bv = (gk < Kb) ? *(const float4*)(bptr + (size_t)kn * ldb)
                           : make_float4(0.f, 0.f, 0.f, 0.f);
        }
        #pragma unroll
        for (int ks = 0; ks < 16; ks += 8) {
            uint32_t a0 = As[ks + tg][mw + gid];
            uint32_t a1 = As[ks + tg][mw + gid + 8];
            uint32_t a2 = As[ks + tg + 4][mw + gid];
            uint32_t a3 = As[ks + tg + 4][mw + gid + 8];
            uint4 B0a = *(const uint4*)&Bs2[ks + tg][gid8];
            uint4 B0b = *(const uint4*)&Bs2[ks + tg][gid8 + 4];
            uint4 B1a = *(const uint4*)&Bs2[ks + tg + 4][gid8];
            uint4 B1b = *(const uint4*)&Bs2[ks + tg + 4][gid8 + 4];
            mma_tf32(acc[0], a0, a1, a2, a3, B0a.x, B1a.x);
            mma_tf32(acc[1], a0, a1, a2, a3, B0a.y, B1a.y);
            mma_tf32(acc[2], a0, a1, a2, a3, B0a.z, B1a.z);
            mma_tf32(acc[3], a0, a1, a2, a3, B0a.w, B1a.w);
            mma_tf32(acc[4], a0, a1, a2, a3, B0b.x, B1b.x);
            mma_tf32(acc[5], a0, a1, a2, a3, B0b.y, B1b.y);
            mma_tf32(acc[6], a0, a1, a2, a3, B0b.z, B1b.z);
            mma_tf32(acc[7], a0, a1, a2, a3, B0b.w, B1b.w);
        }
        __syncthreads();
    }

    #pragma unroll
    for (int j = 0; j < 8; j++) {
        int cc = col0 + j * 8 + tg * 2;
        int r0 = row0 + mw + gid;
        int r1 = r0 + 8;
        if (epi == 0) {
            *(float2*)&C[(size_t)r0 * ldc + cc] = make_float2(acc[j][0], acc[j][1]);
            *(float2*)&C[(size_t)r1 * ldc + cc] = make_float2(acc[j][2], acc[j][3]);
        } else {   // epi 5
            float n0 = C[(size_t)r0 * ldc + cc]     + tanhf(acc[j][0]);
            float n1 = C[(size_t)r0 * ldc + cc + 1] + tanhf(acc[j][1]);
            float n2 = C[(size_t)r1 * ldc + cc]     + tanhf(acc[j][2]);
            float n3 = C[(size_t)r1 * ldc + cc + 1] + tanhf(acc[j][3]);
            C[(size_t)r0 * ldc + cc]     = n0;  g_e[(size_t)r0 * ES + cc]     = n0;
            C[(size_t)r0 * ldc + cc + 1] = n1;  g_e[(size_t)r0 * ES + cc + 1] = n1;
            C[(size_t)r1 * ldc + cc]     = n2;  g_e[(size_t)r1 * ES + cc]     = n2;
            C[(size_t)r1 * ldc + cc + 1] = n3;  g_e[(size_t)r1 * ES + cc + 1] = n3;
        }
    }
}

__global__ void __launch_bounds__(256) qkv_mma_kernel(
    const float* __restrict__ A,
    const float* __restrict__ B0, const float* __restrict__ B1, const float* __restrict__ B2,
    float* __restrict__ C0, float* __restrict__ C1, float* __restrict__ C2)
{
    const float* Bm = (blockIdx.z == 0) ? B0 : (blockIdx.z == 1) ? B1 : B2;
    float* C = (blockIdx.z == 0) ? C0 : (blockIdx.z == 1) ? C1 : C2;
    mma128_body(A, ES, Bm, FEAT, INDIM, C, FEAT, ES, 0);
}

__global__ void __launch_bounds__(256) wo_mma_kernel(
    const float* __restrict__ A, const float* __restrict__ Bm, float* __restrict__ C)
{
    mma128_body(A, FEAT, Bm, FEAT, FEAT, C, FEAT, FEAT, 5);
}

// ------------------------ 64x32-tile fp32 GEMM (Wh: dense + 256 blocks) ------
// epi 3 only (sigm store). 8 FMA per (LDS.128 + LDS.64).
__global__ void __launch_bounds__(256) gemm64x32_kernel(
    const float* __restrict__ A, int lda, const float* __restrict__ Bm, int ldb,
    float* __restrict__ C, int ldc, int K, int useLimit)
{
    int limit = useLimit ? g_waveStart[1] : NEV;
    __shared__ float As[16][68];
    __shared__ float Bs[16][36];
    int tid = threadIdx.x;
    int tx = tid & 15, ty = tid >> 4;
    int row0 = blockIdx.y * 64;
    int col0 = blockIdx.x * 32;
    if (row0 >= limit) return;
    float acc[4][2];
    #pragma unroll
    for (int r = 0; r < 4; r++) { acc[r][0] = 0.f; acc[r][1] = 0.f; }

    int am = tid >> 2;            // 0..63
    int ak = (tid & 3) * 4;       // 0,4,8,12
    int bk = tid >> 4;            // 0..15
    int bn = (tid & 15) * 2;      // 0..30

    for (int kt = 0; kt < K; kt += 16) {
        float4 av = *(const float4*)(A + (size_t)(row0 + am) * lda + kt + ak);
        As[ak + 0][am] = av.x; As[ak + 1][am] = av.y;
        As[ak + 2][am] = av.z; As[ak + 3][am] = av.w;
        float2 bv = *(const float2*)(Bm + (size_t)(kt + bk) * ldb + col0 + bn);
        Bs[bk][bn + 0] = bv.x; Bs[bk][bn + 1] = bv.y;
        __syncthreads();
        #pragma unroll
        for (int kk = 0; kk < 16; kk++) {
            float4 a = *(const float4*)&As[kk][ty * 4];
            float2 b = *(const float2*)&Bs[kk][tx * 2];
            acc[0][0] += a.x * b.x; acc[0][1] += a.x * b.y;
            acc[1][0] += a.y * b.x; acc[1][1] += a.y * b.y;
            acc[2][0] += a.z * b.x; acc[2][1] += a.z * b.y;
            acc[3][0] += a.w * b.x; acc[3][1] += a.w * b.y;
        }
        __syncthreads();
    }
    #pragma unroll
    for (int r = 0; r < 4; r++) {
        int rr = row0 + ty * 4 + r;
        if (rr >= limit) continue;
        int cc = col0 + tx * 2;
        C[(size_t)rr * ldc + cc]     = sigm(acc[r][0]);
        C[(size_t)rr * ldc + cc + 1] = sigm(acc[r][1]);
    }
}

// ------------------------ 32x32-tile fp32 GEMM (occupancy variant) -----------
__global__ void __launch_bounds__(256) gemm32_kernel(
    const float* __restrict__ A, int lda, const float* __restrict__ Bm, int ldb,
    float* __restrict__ C, int ldc, int K, int epi,
    const float* __restrict__ bias, const float* __restrict__ bias2, int useLimit)
{
    int limit = useLimit ? g_waveStart[1] : NEV;
    __shared__ float As[16][36];
    __shared__ float Bs[16][36];
    int tid = threadIdx.x;
    int tx = tid & 15, ty = tid >> 4;
    int row0 = blockIdx.y * 32;
    int col0 = blockIdx.x * 32;
    if (row0 >= limit) return;
    float acc[2][2] = {{0.f, 0.f}, {0.f, 0.f}};

    int am = tid >> 3;
    int ak = (tid & 7) * 2;
    int bk = tid >> 4;
    int bn = (tid & 15) * 2;

    for (int kt = 0; kt < K; kt += 16) {
        float2 av = *(const float2*)(A + (size_t)(row0 + am) * lda + kt + ak);
        As[ak + 0][am] = av.x; As[ak + 1][am] = av.y;
        float2 bv = *(const float2*)(Bm + (size_t)(kt + bk) * ldb + col0 + bn);
        Bs[bk][bn + 0] = bv.x; Bs[bk][bn + 1] = bv.y;
        __syncthreads();
        #pragma unroll
        for (int kk = 0; kk < 16; kk++) {
            float2 a = *(const float2*)&As[kk][ty * 2];
            float2 b = *(const float2*)&Bs[kk][tx * 2];
            acc[0][0] += a.x * b.x; acc[0][1] += a.x * b.y;
            acc[1][0] += a.y * b.x; acc[1][1] += a.y * b.y;
        }
        __syncthreads();
    }
    #pragma unroll
    for (int r = 0; r < 2; r++) {
        int rr = row0 + ty * 2 + r;
        if (rr >= limit) continue;
        #pragma unroll
        for (int c = 0; c < 2; c++) {
            int cc = col0 + tx * 2 + c;
            float v = acc[r][c];
            if (epi == 0)      C[(size_t)rr * ldc + cc] = v;
            else if (epi == 2) C[(size_t)rr * ldc + cc] = fmaxf(v + bias[cc], 0.f);
            else if (epi == 3) C[(size_t)rr * ldc + cc] = sigm(v);
            else if (epi == 4) {
                int ev = g_order[rr];
                g_newS[ev * DIMD + cc] = sigm(g_dts[ev] * bias[cc]  + v);
                g_newO[ev * DIMD + cc] = sigm(g_dto[ev] * bias2[cc] + v);
            }
        }
    }
}

// ------------------------ cleanup: waves >= 1 (persistent, 16 blocks) --------
__global__ void __launch_bounds__(256) cleanup_kernel(
    const int* __restrict__ subj, const int* __restrict__ obj,
    const int* __restrict__ rel,
    const float* __restrict__ mem, const float* __restrict__ remb,
    const float* __restrict__ Wh, const float* __restrict__ Whh,
    const float* __restrict__ Wst, const float* __restrict__ Wot)
{
    __shared__ float s_inp[FEAT];
    __shared__ float s_h[DIML];
    int tid = threadIdx.x;
    for (int w = 1; w < NWAVES; w++) {
        int ws = g_waveStart[w], we = g_waveStart[w + 1];
        if (ws >= NEV) break;
        for (int i = ws + blockIdx.x; i < we; i += 16) {
            int ev = g_order[i];
            int t = ev >> 5, b = ev & 31;
            for (int f = tid; f < FEAT; f += 256) {
                float val;
                if (f < 256) {
                    int which = f >> 7, ff = f & 127;
                    int pred = g_prevRead[t * 64 + which * 32 + b];
                    if (pred < 0) {
                        int ent = which ? obj[b * TT + t] : subj[b * TT + t];
                        val = mem[(size_t)ent * DIMD + ff];
                    } else {
                        int pph = (pred >> 5) & 1;
                        int pev = (pred >> 6) * 32 + (pred & 31);
                        val = pph ? g_newO[pev * DIMD + ff] : g_newS[pev * DIMD + ff];
                    }
                } else {
                    val = remb[rel[b * TT + t] * DIMC + (f - 256)];
                }
                s_inp[f] = val;
            }
            __syncthreads();
            {
                float acc = 0.f;
                #pragma unroll 4
                for (int k = 0; k < FEAT; k++)
                    acc += s_inp[k] * Wh[(size_t)k * DIML + tid];
                s_h[tid] = sigm(acc);
            }
            __syncthreads();
            if (tid < DIMD) {
                float acc = 0.f;
                #pragma unroll 4
                for (int k = 0; k < DIML; k++)
                    acc += s_h[k] * Whh[(size_t)k * DIMD + tid];
                g_newS[ev * DIMD + tid] = sigm(g_dts[ev] * Wst[tid] + acc);
                g_newO[ev * DIMD + tid] = sigm(g_dto[ev] * Wot[tid] + acc);
            }
            __syncthreads();
        }
        __threadfence();
        __syncthreads();
        if (tid == 0) {
            atomicAdd(&g_bar[w], 1);
            while (atomicAdd(&g_bar[w], 0) < 16) { }
        }
        __syncthreads();
        __threadfence();
    }
}

// ------------------------ fused assemble: g_x cols + ALL e cols --------------
__global__ void assemble_e_kernel(const int* __restrict__ rel,
                                  const float* __restrict__ remb,
                                  const float* __restrict__ tim)
{
    int row = blockIdx.x;                  // 0..2047 = b*64 + t
    int tid = threadIdx.x;
    int b = row >> 6, t = row & 63;
    int ev = t * 32 + b;
    float tv = tim[row];
    int rl = rel[row];
    for (int f = tid; f < ES; f += 256) {
        float val;
        if (f < 128)      val = g_newS[ev * DIMD + f];
        else if (f < 256) val = g_newO[ev * DIMD + (f - 128)];
        else if (f < FEAT) val = remb[rl * DIMC + (f - 256)];
        else if (f < FEAT + DIMD) {
            int d = f - FEAT;
            float p = powf(10000.0f, (float)d);
            float nrm = isinf(p) ? 0.0f : (1.0f / p);
            val = sinf(tv * nrm);
        } else if (f == INDIM - 1) val = 1.0f;
        else val = 0.0f;
        g_e[(size_t)row * ES + f] = val;
        if (f < FEAT) g_x[(size_t)row * FEAT + f] = val;
    }
}

// ------------------------ attention (per b,h block) --------------------------
__global__ void __launch_bounds__(256) attn_kernel()
{
    extern __shared__ float sm[];
    float* sq = sm;
    float* sk = sq + 64 * 84;
    float* sv = sk + 64 * 84;
    float* ssc = sv + 64 * 84;
    int b = blockIdx.x, h = blockIdx.y;
    int tid = threadIdx.x;
    const float scale = 0.111803398875f;

    for (int idx = tid; idx < 64 * DH; idx += 256) {
        int i = idx / DH, d = idx - i * DH;
        int row = b * TT + i, col = h * DH + d;
        sq[i * 84 + d] = g_q[(size_t)row * FEAT + col];
        sk[i * 84 + d] = g_k[(size_t)row * FEAT + col];
        sv[i * 84 + d] = g_v[(size_t)row * FEAT + col];
    }
    __syncthreads();
    {
        int i = tid >> 2, jg = tid & 3;
        float acc[16];
        #pragma unroll
        for (int jj = 0; jj < 16; jj++) acc[jj] = 0.f;
        for (int kk = 0; kk < 20; kk++) {
            float4 qv = *(const float4*)&sq[i * 84 + kk * 4];
            #pragma unroll
            for (int jj = 0; jj < 16; jj++) {
                int j = jg * 16 + jj;
                float4 kv = *(const float4*)&sk[j * 84 + kk * 4];
                acc[jj] += qv.x * kv.x + qv.y * kv.y + qv.z * kv.z + qv.w * kv.w;
            }
        }
        #pragma unroll
        for (int jj = 0; jj < 16; jj++)
            ssc[i * 68 + jg * 16 + jj] = acc[jj] * scale;
    }
    __syncthreads();
    // warp-parallel strict-causal softmax: warp w handles rows w, w+8, ...
    {
        int warp = tid >> 5, lane = tid & 31;
        for (int i = warp; i < 64; i += 8) {
            if (i == 0) {
                for (int j = lane; j < 64; j += 32) ssc[j] = 0.f;
                continue;
            }
            float mx = -1e30f;
            for (int j = lane; j < i; j += 32) mx = fmaxf(mx, ssc[i * 68 + j]);
            #pragma unroll
            for (int o = 16; o; o >>= 1)
                mx = fmaxf(mx, __shfl_xor_sync(0xffffffffu, mx, o));
            float sum = 0.f;
            for (int j = lane; j < i; j += 32) {
                float e2 = expf(ssc[i * 68 + j] - mx);
                ssc[i * 68 + j] = e2;
                sum += e2;
            }
            #pragma unroll
            for (int o = 16; o; o >>= 1)
                sum += __shfl_xor_sync(0xffffffffu, sum, o);
            float inv = 1.f / sum;
            for (int j = lane; j < i; j += 32) ssc[i * 68 + j] *= inv;
            for (int j = i + lane; j < 64; j += 32) ssc[i * 68 + j] = 0.f;
        }
    }
    __syncthreads();
    {
        int i = tid >> 2, dg = tid & 3, d0 = dg * 20;
        float acc[20];
        #pragma unroll
        for (int dd = 0; dd < 20; dd++) acc[dd] = 0.f;
        for (int j = 0; j < 64; j++) {
            float a = ssc[i * 68 + j];
            #pragma unroll
            for (int dd = 0; dd < 20; dd++)
                acc[dd] += a * sv[j * 84 + d0 + dd];
        }
        int row = b * TT + i;
        #pragma unroll
        for (int dd = 0; dd < 20; dd++)
            g_ao[(size_t)row * FEAT + h * DH + d0 + dd] = acc[dd];
    }
}

// ------------------------ score head + loss ---------------------------------
__global__ void score2_loss_kernel(const float* __restrict__ W2, const float* __restrict__ b2,
                                   float* __restrict__ dout, int full)
{
    int tid = threadIdx.x;
    int warp = tid >> 5, lane = tid & 31;
    int ev = blockIdx.x * 8 + warp;
    float acc = 0.f;
    for (int f = lane; f < DIMD; f += 32)
        acc += g_s1[ev * DIMD + f] * W2[f];
    #pragma unroll
    for (int o = 16; o; o >>= 1) acc += __shfl_xor_sync(0xffffffffu, acc, o);
    if (lane == 0) {
        float sc = acc + b2[0];
        float lam = fmaxf(sc, 0.f) + log1pf(expf(-fabsf(sc)));
        if (full) dout[1 + ev] = lam;
        g_loss[ev] = -logf(lam + 1e-8f);
    }
}

__global__ void loss_reduce_kernel(float* __restrict__ dout)
{
    __shared__ float s[256];
    int tid = threadIdx.x;
    float a = 0.f;
    for (int i = tid; i < NEV; i += 256) a += g_loss[i];
    s[tid] = a;
    __syncthreads();
    for (int o = 128; o; o >>= 1) {
        if (tid < o) s[tid] += s[tid + o];
        __syncthreads();
    }
    if (tid == 0) dout[0] = s[0] / (float)NEV;
}

// ------------------------ final scatter into mem / latest_time ---------------
__global__ void scatter_kernel(const int* __restrict__ subj, const int* __restrict__ obj,
                               const float* __restrict__ tim,
                               float* __restrict__ outMem, float* __restrict__ outLt)
{
    int pos = blockIdx.x * 256 + threadIdx.x;
    if (pos >= NOCC || !g_isLast[pos]) return;
    int t = pos >> 6, r = pos & 63, ph = r >> 5, b = r & 31;
    int e = ph ? obj[b * TT + t] : subj[b * TT + t];
    int ev = t * 32 + b;
    const float* src = ph ? (g_newO + ev * DIMD) : (g_newS + ev * DIMD);
    float* dst = outMem + (size_t)e * DIMD;
    for (int f = 0; f < DIMD; f++) dst[f] = src[f];
    outLt[e] = tim[b * TT + t];
}

// ------------------------ launch ---------------------------------------------
extern "C" void kernel_launch(void* const* d_in, const int* in_sizes, int n_in,
                              void* d_out, int out_size)
{
    const int*   subj = (const int*)d_in[0];
    const int*   obj  = (const int*)d_in[1];
    const int*   rel  = (const int*)d_in[2];
    const float* tim  = (const float*)d_in[3];
    const float* mem  = (const float*)d_in[4];
    const float* lt   = (const float*)d_in[5];
    const float* remb = (const float*)d_in[6];
    const float* Wh   = (const float*)d_in[7];
    const float* Whh  = (const float*)d_in[8];
    const float* Wst  = (const float*)d_in[9];
    const float* Wot  = (const float*)d_in[10];
    const float* Wq   = (const float*)d_in[11];
    const float* Wk   = (const float*)d_in[12];
    const float* Wv   = (const float*)d_in[13];
    const float* Wo   = (const float*)d_in[14];
    const float* sW1  = (const float*)d_in[15];
    const float* sb1  = (const float*)d_in[16];
    const float* sW2  = (const float*)d_in[17];
    const float* sb2  = (const float*)d_in[18];
    float* dout = (float*)d_out;
    int full = (out_size >= OUT_FULL) ? 1 : 0;

    float *p_x, *p_e, *p_q, *p_k, *p_v, *p_ao, *p_s1, *p_inp, *p_h;
    cudaGetSymbolAddress((void**)&p_x,   g_x);
    cudaGetSymbolAddress((void**)&p_e,   g_e);
    cudaGetSymbolAddress((void**)&p_q,   g_q);
    cudaGetSymbolAddress((void**)&p_k,   g_k);
    cudaGetSymbolAddress((void**)&p_v,   g_v);
    cudaGetSymbolAddress((void**)&p_ao,  g_ao);
    cudaGetSymbolAddress((void**)&p_s1,  g_s1);
    cudaGetSymbolAddress((void**)&p_inp, g_inp);
    cudaGetSymbolAddress((void**)&p_h,   g_h);

    cudaFuncSetAttribute(attn_kernel, cudaFuncAttributeMaxDynamicSharedMemorySize, 81920);

    // ---- phase 1 ----
    links_kernel<<<16, 256>>>(subj, obj, tim, lt);
    depth_compact_kernel<<<1, 256>>>();
    gather0_kernel<<<(NEV * FEAT + 255) / 256, 256>>>(subj, obj, rel, mem, remb);
    // h = sigm(inp @ Wh): 64x32 tiles, grid (8,32)=256 blocks
    gemm64x32_kernel<<<dim3(8, 32), 256>>>(p_inp, FEAT, Wh, DIML, p_h, DIML,
                                           FEAT, 1);
    gemm32_kernel<<<dim3(4, 64), 256>>>(p_h, DIML, Whh, DIMD, p_h /*unused*/, DIMD,
                                        DIML, 4, Wst, Wot, 1);
    cleanup_kernel<<<16, 256>>>(subj, obj, rel, mem, remb, Wh, Whh, Wst, Wot);
    assemble_e_kernel<<<NEV, 256>>>(rel, remb, tim);

    // ---- phase 2 ----
    for (int l = 0; l < 2; l++) {
        const float* wq = Wq + (size_t)l * INDIM * FEAT;
        const float* wk = Wk + (size_t)l * INDIM * FEAT;
        const float* wv = Wv + (size_t)l * INDIM * FEAT;
        const float* wo = Wo + (size_t)l * FEAT * FEAT;
        qkv_mma_kernel<<<dim3(5, 16, 3), 256>>>(p_e, wq, wk, wv, p_q, p_k, p_v);
        attn_kernel<<<dim3(BB, NH), 256, 81920>>>();
        wo_mma_kernel<<<dim3(5, 16), 256>>>(p_ao, wo, p_x);
    }

    // ---- score head (fp32 for accuracy) ----
    gemm32_kernel<<<dim3(4, 64), 256>>>(p_x, FEAT, sW1, DIMD, p_s1, DIMD,
                                        FEAT, 2, sb1, nullptr, 0);
    score2_loss_kernel<<<NEV / 8, 256>>>(sW2, sb2, dout, full);
    loss_reduce_kernel<<<1, 256>>>(dout);

    // ---- final mem / latest_time outputs ----
    if (full) {
        float* outMem = dout + 1 + NEV;
        float* outLt  = outMem + (size_t)200000 * DIMD;
        cudaMemcpyAsync(outMem, mem, (size_t)200000 * DIMD * sizeof(float),
                        cudaMemcpyDeviceToDevice, 0);
        cudaMemcpyAsync(outLt, lt, 200000 * sizeof(float),
                        cudaMemcpyDeviceToDevice, 0);
        scatter_kernel<<<16, 256>>>(subj, obj, tim, outMem, outLt);
    }
}

// round 17
// speedup vs baseline: 1.2942x; 1.1577x over previous
#include <cuda_runtime.h>
#include <cuda_bf16.h>
#include <math.h>
#include <stdint.h>

#define BB      32
#define TT      64
#define NEV     2048      // B*T events
#define NOCC    4096      // 2*B*T occurrences
#define DIMD    128
#define DIMC    64
#define DIML    256
#define FEAT    320
#define INDIM   449
#define ES      464       // padded e row stride (div by 16)
#define NH      4
#define DH      80
#define NWAVES  16
#define OUT_FULL 25802049  // 1 + 2048 + 200000*128 + 200000

// ------------------------ device scratch ------------------------------------
__device__ int   g_prevRead[NOCC];
__device__ int   g_isLast[NOCC];
__device__ int   g_depth[NEV];
__device__ int   g_order[NEV];
__device__ int   g_waveStart[NWAVES + 1];
__device__ int   g_bar[NWAVES];
__device__ float g_dts[NEV];
__device__ float g_dto[NEV];
__device__ float g_inp[NEV * FEAT];
__device__ float g_h[NEV * DIML];
__device__ float g_newS[NEV * DIMD];
__device__ float g_newO[NEV * DIMD];
__device__ float g_x[NEV * FEAT];
__device__ float g_e[NEV * ES + 64];
__device__ float g_q[NEV * FEAT];
__device__ float g_k[NEV * FEAT];
__device__ float g_v[NEV * FEAT];
__device__ float g_ao[NEV * FEAT];
__device__ float g_s1[NEV * DIMD];
__device__ float g_loss[NEV];

__device__ __forceinline__ float sigm(float x) { return 1.f / (1.f + expf(-x)); }

__device__ __forceinline__ uint32_t f2tf32(float f) {
    uint32_t u; asm("cvt.rna.tf32.f32 %0, %1;" : "=r"(u) : "f"(f)); return u;
}
__device__ __forceinline__ void mma_tf32(float* c, uint32_t a0, uint32_t a1,
                                         uint32_t a2, uint32_t a3,
                                         uint32_t b0, uint32_t b1) {
    asm volatile(
        "mma.sync.aligned.m16n8k8.row.col.f32.tf32.tf32.f32 "
        "{%0,%1,%2,%3}, {%4,%5,%6,%7}, {%8,%9}, {%0,%1,%2,%3};"
        : "+f"(c[0]), "+f"(c[1]), "+f"(c[2]), "+f"(c[3])
        : "r"(a0), "r"(a1), "r"(a2), "r"(a3), "r"(b0), "r"(b1));
}

// ------------------------ kernel A1: occurrence links (warp-per-pos) ---------
// occurrence pos = t*64 + phase*32 + b   (phase 0 = subject write, 1 = object)
// grid 512 x 256: each warp handles one pos; lanes stride the 4096-entry table.
__global__ void __launch_bounds__(256) links_kernel(
    const int* __restrict__ subj, const int* __restrict__ obj,
    const float* __restrict__ tim, const float* __restrict__ lt)
{
    __shared__ int s_ent[NOCC];
    int tid = threadIdx.x;
    for (int p = tid; p < NOCC; p += 256) {
        int t = p >> 6, r = p & 63, ph = r >> 5, b = r & 31;
        s_ent[p] = ph ? obj[b * TT + t] : subj[b * TT + t];
    }
    __syncthreads();
    int warp = tid >> 5, lane = tid & 31;
    int pos = blockIdx.x * 8 + warp;
    int e = s_ent[pos];
    int t = pos >> 6, r = pos & 63, ph = r >> 5, b = r & 31;
    int stepStart = t * 64;
    int prevR = -1, later = 0;
    for (int p2 = lane; p2 < NOCC; p2 += 32) {
        if (s_ent[p2] == e) {
            if (p2 < stepStart && p2 > prevR) prevR = p2;
            if (p2 > pos) later = 1;
        }
    }
    #pragma unroll
    for (int o = 16; o; o >>= 1) {
        prevR = max(prevR, __shfl_xor_sync(0xffffffffu, prevR, o));
        later |= __shfl_xor_sync(0xffffffffu, later, o);
    }
    if (lane == 0) {
        g_prevRead[pos] = prevR;
        g_isLast[pos] = !later;
        float ltv = (prevR < 0) ? lt[e] : tim[(prevR & 31) * TT + (prevR >> 6)];
        float dt = tim[b * TT + t] - ltv;
        int ev = t * 32 + b;
        if (ph == 0) g_dts[ev] = dt; else g_dto[ev] = dt;
    }
}

// ------------------------ kernel A2: depths + compaction ---------------------
__global__ void depth_compact_kernel()
{
    __shared__ int s_d[NEV];
    __shared__ int s_ps[NEV];
    __shared__ int s_po[NEV];
    __shared__ int s_cnt[NWAVES];
    __shared__ int s_off[NWAVES + 1];
    __shared__ int s_n;
    int tid = threadIdx.x;
    for (int ev = tid; ev < NEV; ev += 256) {
        int t = ev >> 5, b = ev & 31;
        int ps = g_prevRead[t * 64 + b];
        int po = g_prevRead[t * 64 + 32 + b];
        s_ps[ev] = (ps < 0) ? -1 : ((ps >> 6) * 32 + (ps & 31));
        s_po[ev] = (po < 0) ? -1 : ((po >> 6) * 32 + (po & 31));
        s_d[ev] = -1;
    }
    if (tid < NWAVES) { s_cnt[tid] = 0; g_bar[tid] = 0; }
    if (tid == 0) s_n = 0;
    __syncthreads();
    for (int pass = 0; pass < 32; pass++) {
        for (int ev = tid; ev < NEV; ev += 256) {
            if (s_d[ev] < 0) {
                int a = s_ps[ev], b2 = s_po[ev];
                int da = (a < 0) ? -1 : s_d[a];
                int db = (b2 < 0) ? -1 : s_d[b2];
                bool ra = (a < 0) || (da >= 0);
                bool rb = (b2 < 0) || (db >= 0);
                if (ra && rb) { s_d[ev] = max(da, db) + 1; atomicAdd(&s_n, 1); }
            }
        }
        __syncthreads();
        if (s_n >= NEV) break;
    }
    for (int ev = tid; ev < NEV; ev += 256) {
        int d = s_d[ev];
        d = (d < 0) ? 0 : ((d > NWAVES - 1) ? NWAVES - 1 : d);
        s_d[ev] = d;
        g_depth[ev] = d;
        atomicAdd(&s_cnt[d], 1);
    }
    __syncthreads();
    if (tid == 0) {
        int acc = 0;
        for (int w = 0; w < NWAVES; w++) { s_off[w] = acc; acc += s_cnt[w]; }
        s_off[NWAVES] = acc;
        for (int w = 0; w <= NWAVES; w++) g_waveStart[w] = s_off[w];
        for (int w = 0; w < NWAVES; w++) s_cnt[w] = s_off[w];
    }
    __syncthreads();
    for (int ev = tid; ev < NEV; ev += 256) {
        int pos = atomicAdd(&s_cnt[s_d[ev]], 1);
        g_order[pos] = ev;
    }
}

// ------------------------ gather wave-0 inputs -------------------------------
__global__ void gather0_kernel(const int* __restrict__ subj, const int* __restrict__ obj,
                               const int* __restrict__ rel,
                               const float* __restrict__ mem, const float* __restrict__ remb)
{
    int idx = blockIdx.x * 256 + threadIdx.x;
    if (idx >= NEV * FEAT) return;
    int row = idx / FEAT, f = idx - row * FEAT;
    if (row >= g_waveStart[1]) return;
    int ev = g_order[row];
    int t = ev >> 5, b = ev & 31;
    float val;
    if (f < 256) {
        int which = f >> 7, ff = f & 127;
        int ent = which ? obj[b * TT + t] : subj[b * TT + t];
        val = mem[(size_t)ent * DIMD + ff];
    } else {
        val = remb[rel[b * TT + t] * DIMC + (f - 256)];
    }
    g_inp[row * FEAT + f] = val;
}

// ------------------------ tf32 tensor-core GEMM (128x64 tile) ----------------
// Register-prefetch of next k-tile overlaps LDG latency with mma phase.
// epi: 0 store; 5: C += tanh(acc) AND mirror into g_e
__device__ __forceinline__ void mma128_body(
    const float* __restrict__ A, int lda,
    const float* __restrict__ Bm, int ldb, int Kb,
    float* __restrict__ C, int ldc, int K, int epi)
{
    __shared__ uint32_t As[16][136];
    __shared__ uint32_t Bs2[16][68];
    int tid = threadIdx.x;
    int lane = tid & 31, warp = tid >> 5;
    int tg = lane & 3, gid = lane >> 2;
    int row0 = blockIdx.y * 128;
    int col0 = blockIdx.x * 64;
    int mw = warp * 16;
    int gid8 = gid * 8;

    float acc[8][4];
    #pragma unroll
    for (int j = 0; j < 8; j++)
        #pragma unroll
        for (int c = 0; c < 4; c++) acc[j][c] = 0.f;

    int arow = tid >> 1;
    int akoff = (tid & 1) * 8;
    int bk = tid >> 4;
    int bn = (tid & 15) * 4;

    const float* aptr = A + (size_t)(row0 + arow) * lda + akoff;
    const float* bptr = Bm + (size_t)bk * ldb + col0 + bn;

    float4 av0 = *(const float4*)(aptr);
    float4 av1 = *(const float4*)(aptr + 4);
    float4 bv = (bk < Kb) ? *(const float4*)(bptr) : make_float4(0.f, 0.f, 0.f, 0.f);

    for (int kt = 0; kt < K; kt += 16) {
        As[akoff + 0][arow] = f2tf32(av0.x);
        As[akoff + 1][arow] = f2tf32(av0.y);
        As[akoff + 2][arow] = f2tf32(av0.z);
        As[akoff + 3][arow] = f2tf32(av0.w);
        As[akoff + 4][arow] = f2tf32(av1.x);
        As[akoff + 5][arow] = f2tf32(av1.y);
        As[akoff + 6][arow] = f2tf32(av1.z);
        As[akoff + 7][arow] = f2tf32(av1.w);
        Bs2[bk][((bn + 0) & 7) * 8 + ((bn + 0) >> 3)] = f2tf32(bv.x);
        Bs2[bk][((bn + 1) & 7) * 8 + ((bn + 1) >> 3)] = f2tf32(bv.y);
        Bs2[bk][((bn + 2) & 7) * 8 + ((bn + 2) >> 3)] = f2tf32(bv.z);
        Bs2[bk][((bn + 3) & 7) * 8 + ((bn + 3) >> 3)] = f2tf32(bv.w);
        __syncthreads();
        int kn = kt + 16;
        if (kn < K) {
            av0 = *(const float4*)(aptr + kn);
            av1 = *(const float4*)(aptr + kn + 4);
            int gk = kn + bk;
            bv = (gk < Kb) ? *(const float4*)(bptr + (size_t)kn * ldb)
                           : make_float4(0.f, 0.f, 0.f, 0.f);
        }
        #pragma unroll
        for (int ks = 0; ks < 16; ks += 8) {
            uint32_t a0 = As[ks + tg][mw + gid];
            uint32_t a1 = As[ks + tg][mw + gid + 8];
            uint32_t a2 = As[ks + tg + 4][mw + gid];
            uint32_t a3 = As[ks + tg + 4][mw + gid + 8];
            uint4 B0a = *(const uint4*)&Bs2[ks + tg][gid8];
            uint4 B0b = *(const uint4*)&Bs2[ks + tg][gid8 + 4];
            uint4 B1a = *(const uint4*)&Bs2[ks + tg + 4][gid8];
            uint4 B1b = *(const uint4*)&Bs2[ks + tg + 4][gid8 + 4];
            mma_tf32(acc[0], a0, a1, a2, a3, B0a.x, B1a.x);
            mma_tf32(acc[1], a0, a1, a2, a3, B0a.y, B1a.y);
            mma_tf32(acc[2], a0, a1, a2, a3, B0a.z, B1a.z);
            mma_tf32(acc[3], a0, a1, a2, a3, B0a.w, B1a.w);
            mma_tf32(acc[4], a0, a1, a2, a3, B0b.x, B1b.x);
            mma_tf32(acc[5], a0, a1, a2, a3, B0b.y, B1b.y);
            mma_tf32(acc[6], a0, a1, a2, a3, B0b.z, B1b.z);
            mma_tf32(acc[7], a0, a1, a2, a3, B0b.w, B1b.w);
        }
        __syncthreads();
    }

    #pragma unroll
    for (int j = 0; j < 8; j++) {
        int cc = col0 + j * 8 + tg * 2;
        int r0 = row0 + mw + gid;
        int r1 = r0 + 8;
        if (epi == 0) {
            *(float2*)&C[(size_t)r0 * ldc + cc] = make_float2(acc[j][0], acc[j][1]);
            *(float2*)&C[(size_t)r1 * ldc + cc] = make_float2(acc[j][2], acc[j][3]);
        } else {   // epi 5
            float n0 = C[(size_t)r0 * ldc + cc]     + tanhf(acc[j][0]);
            float n1 = C[(size_t)r0 * ldc + cc + 1] + tanhf(acc[j][1]);
            float n2 = C[(size_t)r1 * ldc + cc]     + tanhf(acc[j][2]);
            float n3 = C[(size_t)r1 * ldc + cc + 1] + tanhf(acc[j][3]);
            C[(size_t)r0 * ldc + cc]     = n0;  g_e[(size_t)r0 * ES + cc]     = n0;
            C[(size_t)r0 * ldc + cc + 1] = n1;  g_e[(size_t)r0 * ES + cc + 1] = n1;
            C[(size_t)r1 * ldc + cc]     = n2;  g_e[(size_t)r1 * ES + cc]     = n2;
            C[(size_t)r1 * ldc + cc + 1] = n3;  g_e[(size_t)r1 * ES + cc + 1] = n3;
        }
    }
}

__global__ void __launch_bounds__(256) qkv_mma_kernel(
    const float* __restrict__ A,
    const float* __restrict__ B0, const float* __restrict__ B1, const float* __restrict__ B2,
    float* __restrict__ C0, float* __restrict__ C1, float* __restrict__ C2)
{
    const float* Bm = (blockIdx.z == 0) ? B0 : (blockIdx.z == 1) ? B1 : B2;
    float* C = (blockIdx.z == 0) ? C0 : (blockIdx.z == 1) ? C1 : C2;
    mma128_body(A, ES, Bm, FEAT, INDIM, C, FEAT, ES, 0);
}

__global__ void __launch_bounds__(256) wo_mma_kernel(
    const float* __restrict__ A, const float* __restrict__ Bm, float* __restrict__ C)
{
    mma128_body(A, FEAT, Bm, FEAT, FEAT, C, FEAT, FEAT, 5);
}

// ------------------------ 64x32-tile fp32 GEMM (Wh) --------------------------
__global__ void __launch_bounds__(256) gemm64x32_kernel(
    const float* __restrict__ A, int lda, const float* __restrict__ Bm, int ldb,
    float* __restrict__ C, int ldc, int K, int useLimit)
{
    int limit = useLimit ? g_waveStart[1] : NEV;
    __shared__ float As[16][68];
    __shared__ float Bs[16][36];
    int tid = threadIdx.x;
    int tx = tid & 15, ty = tid >> 4;
    int row0 = blockIdx.y * 64;
    int col0 = blockIdx.x * 32;
    if (row0 >= limit) return;
    float acc[4][2];
    #pragma unroll
    for (int r = 0; r < 4; r++) { acc[r][0] = 0.f; acc[r][1] = 0.f; }

    int am = tid >> 2;
    int ak = (tid & 3) * 4;
    int bk = tid >> 4;
    int bn = (tid & 15) * 2;

    for (int kt = 0; kt < K; kt += 16) {
        float4 av = *(const float4*)(A + (size_t)(row0 + am) * lda + kt + ak);
        As[ak + 0][am] = av.x; As[ak + 1][am] = av.y;
        As[ak + 2][am] = av.z; As[ak + 3][am] = av.w;
        float2 bv = *(const float2*)(Bm + (size_t)(kt + bk) * ldb + col0 + bn);
        Bs[bk][bn + 0] = bv.x; Bs[bk][bn + 1] = bv.y;
        __syncthreads();
        #pragma unroll
        for (int kk = 0; kk < 16; kk++) {
            float4 a = *(const float4*)&As[kk][ty * 4];
            float2 b = *(const float2*)&Bs[kk][tx * 2];
            acc[0][0] += a.x * b.x; acc[0][1] += a.x * b.y;
            acc[1][0] += a.y * b.x; acc[1][1] += a.y * b.y;
            acc[2][0] += a.z * b.x; acc[2][1] += a.z * b.y;
            acc[3][0] += a.w * b.x; acc[3][1] += a.w * b.y;
        }
        __syncthreads();
    }
    #pragma unroll
    for (int r = 0; r < 4; r++) {
        int rr = row0 + ty * 4 + r;
        if (rr >= limit) continue;
        int cc = col0 + tx * 2;
        C[(size_t)rr * ldc + cc]     = sigm(acc[r][0]);
        C[(size_t)rr * ldc + cc + 1] = sigm(acc[r][1]);
    }
}

// ------------------------ 32x32-tile fp32 GEMM (occupancy variant) -----------
__global__ void __launch_bounds__(256) gemm32_kernel(
    const float* __restrict__ A, int lda, const float* __restrict__ Bm, int ldb,
    float* __restrict__ C, int ldc, int K, int epi,
    const float* __restrict__ bias, const float* __restrict__ bias2, int useLimit)
{
    int limit = useLimit ? g_waveStart[1] : NEV;
    __shared__ float As[16][36];
    __shared__ float Bs[16][36];
    int tid = threadIdx.x;
    int tx = tid & 15, ty = tid >> 4;
    int row0 = blockIdx.y * 32;
    int col0 = blockIdx.x * 32;
    if (row0 >= limit) return;
    float acc[2][2] = {{0.f, 0.f}, {0.f, 0.f}};

    int am = tid >> 3;
    int ak = (tid & 7) * 2;
    int bk = tid >> 4;
    int bn = (tid & 15) * 2;

    for (int kt = 0; kt < K; kt += 16) {
        float2 av = *(const float2*)(A + (size_t)(row0 + am) * lda + kt + ak);
        As[ak + 0][am] = av.x; As[ak + 1][am] = av.y;
        float2 bv = *(const float2*)(Bm + (size_t)(kt + bk) * ldb + col0 + bn);
        Bs[bk][bn + 0] = bv.x; Bs[bk][bn + 1] = bv.y;
        __syncthreads();
        #pragma unroll
        for (int kk = 0; kk < 16; kk++) {
            float2 a = *(const float2*)&As[kk][ty * 2];
            float2 b = *(const float2*)&Bs[kk][tx * 2];
            acc[0][0] += a.x * b.x; acc[0][1] += a.x * b.y;
            acc[1][0] += a.y * b.x; acc[1][1] += a.y * b.y;
        }
        __syncthreads();
    }
    #pragma unroll
    for (int r = 0; r < 2; r++) {
        int rr = row0 + ty * 2 + r;
        if (rr >= limit) continue;
        #pragma unroll
        for (int c = 0; c < 2; c++) {
            int cc = col0 + tx * 2 + c;
            float v = acc[r][c];
            if (epi == 0)      C[(size_t)rr * ldc + cc] = v;
            else if (epi == 2) C[(size_t)rr * ldc + cc] = fmaxf(v + bias[cc], 0.f);
            else if (epi == 3) C[(size_t)rr * ldc + cc] = sigm(v);
            else if (epi == 4) {
                int ev = g_order[rr];
                g_newS[ev * DIMD + cc] = sigm(g_dts[ev] * bias[cc]  + v);
                g_newO[ev * DIMD + cc] = sigm(g_dto[ev] * bias2[cc] + v);
            }
        }
    }
}

// ------------------------ cleanup: waves >= 1 (persistent, 16 blocks) --------
__global__ void __launch_bounds__(256) cleanup_kernel(
    const int* __restrict__ subj, const int* __restrict__ obj,
    const int* __restrict__ rel,
    const float* __restrict__ mem, const float* __restrict__ remb,
    const float* __restrict__ Wh, const float* __restrict__ Whh,
    const float* __restrict__ Wst, const float* __restrict__ Wot)
{
    __shared__ float s_inp[FEAT];
    __shared__ float s_h[DIML];
    int tid = threadIdx.x;
    for (int w = 1; w < NWAVES; w++) {
        int ws = g_waveStart[w], we = g_waveStart[w + 1];
        if (ws >= NEV) break;
        for (int i = ws + blockIdx.x; i < we; i += 16) {
            int ev = g_order[i];
            int t = ev >> 5, b = ev & 31;
            for (int f = tid; f < FEAT; f += 256) {
                float val;
                if (f < 256) {
                    int which = f >> 7, ff = f & 127;
                    int pred = g_prevRead[t * 64 + which * 32 + b];
                    if (pred < 0) {
                        int ent = which ? obj[b * TT + t] : subj[b * TT + t];
                        val = mem[(size_t)ent * DIMD + ff];
                    } else {
                        int pph = (pred >> 5) & 1;
                        int pev = (pred >> 6) * 32 + (pred & 31);
                        val = pph ? g_newO[pev * DIMD + ff] : g_newS[pev * DIMD + ff];
                    }
                } else {
                    val = remb[rel[b * TT + t] * DIMC + (f - 256)];
                }
                s_inp[f] = val;
            }
            __syncthreads();
            {
                float acc = 0.f;
                #pragma unroll 4
                for (int k = 0; k < FEAT; k++)
                    acc += s_inp[k] * Wh[(size_t)k * DIML + tid];
                s_h[tid] = sigm(acc);
            }
            __syncthreads();
            if (tid < DIMD) {
                float acc = 0.f;
                #pragma unroll 4
                for (int k = 0; k < DIML; k++)
                    acc += s_h[k] * Whh[(size_t)k * DIMD + tid];
                g_newS[ev * DIMD + tid] = sigm(g_dts[ev] * Wst[tid] + acc);
                g_newO[ev * DIMD + tid] = sigm(g_dto[ev] * Wot[tid] + acc);
            }
            __syncthreads();
        }
        __threadfence();
        __syncthreads();
        if (tid == 0) {
            atomicAdd(&g_bar[w], 1);
            while (atomicAdd(&g_bar[w], 0) < 16) { }
        }
        __syncthreads();
        __threadfence();
    }
}

// ------------------------ fused assemble: g_x cols + ALL e cols --------------
__global__ void assemble_e_kernel(const int* __restrict__ rel,
                                  const float* __restrict__ remb,
                                  const float* __restrict__ tim)
{
    int row = blockIdx.x;
    int tid = threadIdx.x;
    int b = row >> 6, t = row & 63;
    int ev = t * 32 + b;
    float tv = tim[row];
    int rl = rel[row];
    for (int f = tid; f < ES; f += 256) {
        float val;
        if (f < 128)      val = g_newS[ev * DIMD + f];
        else if (f < 256) val = g_newO[ev * DIMD + (f - 128)];
        else if (f < FEAT) val = remb[rl * DIMC + (f - 256)];
        else if (f < FEAT + DIMD) {
            int d = f - FEAT;
            float p = powf(10000.0f, (float)d);
            float nrm = isinf(p) ? 0.0f : (1.0f / p);
            val = sinf(tv * nrm);
        } else if (f == INDIM - 1) val = 1.0f;
        else val = 0.0f;
        g_e[(size_t)row * ES + f] = val;
        if (f < FEAT) g_x[(size_t)row * FEAT + f] = val;
    }
}

// ------------------------ attention (per b,h block) --------------------------
__global__ void __launch_bounds__(256) attn_kernel()
{
    extern __shared__ float sm[];
    float* sq = sm;
    float* sk = sq + 64 * 84;
    float* sv = sk + 64 * 84;
    float* ssc = sv + 64 * 84;
    int b = blockIdx.x, h = blockIdx.y;
    int tid = threadIdx.x;
    const float scale = 0.111803398875f;

    for (int idx = tid; idx < 64 * DH; idx += 256) {
        int i = idx / DH, d = idx - i * DH;
        int row = b * TT + i, col = h * DH + d;
        sq[i * 84 + d] = g_q[(size_t)row * FEAT + col];
        sk[i * 84 + d] = g_k[(size_t)row * FEAT + col];
        sv[i * 84 + d] = g_v[(size_t)row * FEAT + col];
    }
    __syncthreads();
    {
        int i = tid >> 2, jg = tid & 3;
        float acc[16];
        #pragma unroll
        for (int jj = 0; jj < 16; jj++) acc[jj] = 0.f;
        for (int kk = 0; kk < 20; kk++) {
            float4 qv = *(const float4*)&sq[i * 84 + kk * 4];
            #pragma unroll
            for (int jj = 0; jj < 16; jj++) {
                int j = jg * 16 + jj;
                float4 kv = *(const float4*)&sk[j * 84 + kk * 4];
                acc[jj] += qv.x * kv.x + qv.y * kv.y + qv.z * kv.z + qv.w * kv.w;
            }
        }
        #pragma unroll
        for (int jj = 0; jj < 16; jj++)
            ssc[i * 68 + jg * 16 + jj] = acc[jj] * scale;
    }
    __syncthreads();
    // warp-parallel strict-causal softmax
    {
        int warp = tid >> 5, lane = tid & 31;
        for (int i = warp; i < 64; i += 8) {
            if (i == 0) {
                for (int j = lane; j < 64; j += 32) ssc[j] = 0.f;
                continue;
            }
            float mx = -1e30f;
            for (int j = lane; j < i; j += 32) mx = fmaxf(mx, ssc[i * 68 + j]);
            #pragma unroll
            for (int o = 16; o; o >>= 1)
                mx = fmaxf(mx, __shfl_xor_sync(0xffffffffu, mx, o));
            float sum = 0.f;
            for (int j = lane; j < i; j += 32) {
                float e2 = expf(ssc[i * 68 + j] - mx);
                ssc[i * 68 + j] = e2;
                sum += e2;
            }
            #pragma unroll
            for (int o = 16; o; o >>= 1)
                sum += __shfl_xor_sync(0xffffffffu, sum, o);
            float inv = 1.f / sum;
            for (int j = lane; j < i; j += 32) ssc[i * 68 + j] *= inv;
            for (int j = i + lane; j < 64; j += 32) ssc[i * 68 + j] = 0.f;
        }
    }
    __syncthreads();
    {
        int i = tid >> 2, dg = tid & 3, d0 = dg * 20;
        float acc[20];
        #pragma unroll
        for (int dd = 0; dd < 20; dd++) acc[dd] = 0.f;
        for (int j = 0; j < 64; j++) {
            float a = ssc[i * 68 + j];
            #pragma unroll
            for (int dd = 0; dd < 20; dd++)
                acc[dd] += a * sv[j * 84 + d0 + dd];
        }
        int row = b * TT + i;
        #pragma unroll
        for (int dd = 0; dd < 20; dd++)
            g_ao[(size_t)row * FEAT + h * DH + d0 + dd] = acc[dd];
    }
}

// ------------------------ score head + loss ---------------------------------
__global__ void score2_loss_kernel(const float* __restrict__ W2, const float* __restrict__ b2,
                                   float* __restrict__ dout, int full)
{
    int tid = threadIdx.x;
    int warp = tid >> 5, lane = tid & 31;
    int ev = blockIdx.x * 8 + warp;
    float acc = 0.f;
    for (int f = lane; f < DIMD; f += 32)
        acc += g_s1[ev * DIMD + f] * W2[f];
    #pragma unroll
    for (int o = 16; o; o >>= 1) acc += __shfl_xor_sync(0xffffffffu, acc, o);
    if (lane == 0) {
        float sc = acc + b2[0];
        float lam = fmaxf(sc, 0.f) + log1pf(expf(-fabsf(sc)));
        if (full) dout[1 + ev] = lam;
        g_loss[ev] = -logf(lam + 1e-8f);
    }
}

__global__ void loss_reduce_kernel(float* __restrict__ dout)
{
    __shared__ float s[256];
    int tid = threadIdx.x;
    float a = 0.f;
    for (int i = tid; i < NEV; i += 256) a += g_loss[i];
    s[tid] = a;
    __syncthreads();
    for (int o = 128; o; o >>= 1) {
        if (tid < o) s[tid] += s[tid + o];
        __syncthreads();
    }
    if (tid == 0) dout[0] = s[0] / (float)NEV;
}

// ------------------------ final scatter (warp-per-occurrence, coalesced) -----
__global__ void scatter_kernel(const int* __restrict__ subj, const int* __restrict__ obj,
                               const float* __restrict__ tim,
                               float* __restrict__ outMem, float* __restrict__ outLt)
{
    int tid = threadIdx.x;
    int warp = tid >> 5, lane = tid & 31;
    int gw = blockIdx.x * 8 + warp;          // 512 blocks x 8 warps = 4096
    if (gw >= NOCC || !g_isLast[gw]) return;
    int t = gw >> 6, r = gw & 63, ph = r >> 5, b = r & 31;
    int e = ph ? obj[b * TT + t] : subj[b * TT + t];
    int ev = t * 32 + b;
    const float* src = ph ? (g_newO + ev * DIMD) : (g_newS + ev * DIMD);
    float* dst = outMem + (size_t)e * DIMD;
    #pragma unroll
    for (int f = lane; f < DIMD; f += 32) dst[f] = src[f];
    if (lane == 0) outLt[e] = tim[b * TT + t];
}

// ------------------------ launch ---------------------------------------------
extern "C" void kernel_launch(void* const* d_in, const int* in_sizes, int n_in,
                              void* d_out, int out_size)
{
    const int*   subj = (const int*)d_in[0];
    const int*   obj  = (const int*)d_in[1];
    const int*   rel  = (const int*)d_in[2];
    const float* tim  = (const float*)d_in[3];
    const float* mem  = (const float*)d_in[4];
    const float* lt   = (const float*)d_in[5];
    const float* remb = (const float*)d_in[6];
    const float* Wh   = (const float*)d_in[7];
    const float* Whh  = (const float*)d_in[8];
    const float* Wst  = (const float*)d_in[9];
    const float* Wot  = (const float*)d_in[10];
    const float* Wq   = (const float*)d_in[11];
    const float* Wk   = (const float*)d_in[12];
    const float* Wv   = (const float*)d_in[13];
    const float* Wo   = (const float*)d_in[14];
    const float* sW1  = (const float*)d_in[15];
    const float* sb1  = (const float*)d_in[16];
    const float* sW2  = (const float*)d_in[17];
    const float* sb2  = (const float*)d_in[18];
    float* dout = (float*)d_out;
    int full = (out_size >= OUT_FULL) ? 1 : 0;

    float *p_x, *p_e, *p_q, *p_k, *p_v, *p_ao, *p_s1, *p_inp, *p_h;
    cudaGetSymbolAddress((void**)&p_x,   g_x);
    cudaGetSymbolAddress((void**)&p_e,   g_e);
    cudaGetSymbolAddress((void**)&p_q,   g_q);
    cudaGetSymbolAddress((void**)&p_k,   g_k);
    cudaGetSymbolAddress((void**)&p_v,   g_v);
    cudaGetSymbolAddress((void**)&p_ao,  g_ao);
    cudaGetSymbolAddress((void**)&p_s1,  g_s1);
    cudaGetSymbolAddress((void**)&p_inp, g_inp);
    cudaGetSymbolAddress((void**)&p_h,   g_h);

    cudaFuncSetAttribute(attn_kernel, cudaFuncAttributeMaxDynamicSharedMemorySize, 81920);

    // ---- phase 1 ----
    links_kernel<<<512, 256>>>(subj, obj, tim, lt);
    depth_compact_kernel<<<1, 256>>>();
    gather0_kernel<<<(NEV * FEAT + 255) / 256, 256>>>(subj, obj, rel, mem, remb);
    gemm64x32_kernel<<<dim3(8, 32), 256>>>(p_inp, FEAT, Wh, DIML, p_h, DIML,
                                           FEAT, 1);
    gemm32_kernel<<<dim3(4, 64), 256>>>(p_h, DIML, Whh, DIMD, p_h /*unused*/, DIMD,
                                        DIML, 4, Wst, Wot, 1);
    cleanup_kernel<<<16, 256>>>(subj, obj, rel, mem, remb, Wh, Whh, Wst, Wot);
    assemble_e_kernel<<<NEV, 256>>>(rel, remb, tim);

    // ---- phase 2 ----
    for (int l = 0; l < 2; l++) {
        const float* wq = Wq + (size_t)l * INDIM * FEAT;
        const float* wk = Wk + (size_t)l * INDIM * FEAT;
        const float* wv = Wv + (size_t)l * INDIM * FEAT;
        const float* wo = Wo + (size_t)l * FEAT * FEAT;
        qkv_mma_kernel<<<dim3(5, 16, 3), 256>>>(p_e, wq, wk, wv, p_q, p_k, p_v);
        attn_kernel<<<dim3(BB, NH), 256, 81920>>>();
        wo_mma_kernel<<<dim3(5, 16), 256>>>(p_ao, wo, p_x);
    }

    // ---- score head ----
    gemm32_kernel<<<dim3(4, 64), 256>>>(p_x, FEAT, sW1, DIMD, p_s1, DIMD,
                                        FEAT, 2, sb1, nullptr, 0);
    score2_loss_kernel<<<NEV / 8, 256>>>(sW2, sb2, dout, full);
    loss_reduce_kernel<<<1, 256>>>(dout);

    // ---- final mem / latest_time outputs ----
    if (full) {
        float* outMem = dout + 1 + NEV;
        float* outLt  = outMem + (size_t)200000 * DIMD;
        cudaMemcpyAsync(outMem, mem, (size_t)200000 * DIMD * sizeof(float),
                        cudaMemcpyDeviceToDevice, 0);
        cudaMemcpyAsync(outLt, lt, 200000 * sizeof(float),
                        cudaMemcpyDeviceToDevice, 0);
        scatter_kernel<<<512, 256>>>(subj, obj, tim, outMem, outLt);
    }
}